// round 2
// baseline (speedup 1.0000x reference)
#include <cuda_runtime.h>
#include <cuda_bf16.h>
#include <cstdint>

// ---------------------------------------------------------------------------
// CrossAttention: B=32, N=1536, M=80, H=8, C=64, inner=512, QD=320, KD=VD=768
// Pipeline:
//   1) q  = x    @ Wq^T   (49152 x 512, K=320)
//   2) kp = key  @ Wk^T   ( 2560 x 512, K=768)
//   3) vp = val  @ Wv^T   ( 2560 x 512, K=768)
//   4) attention (fused scores + mask + box bias + softmax + PV)
//   5) out = ao @ Wo^T + bo (49152 x 320, K=512)
// road bias is constant over the key axis -> softmax-invariant -> dropped.
// NOTE: harness converts the jax bool mask to int32 (only f32/i32/bf16 exist).
// ---------------------------------------------------------------------------

#define B_SZ   32
#define N_SZ   1536
#define M_SZ   80
#define HEADS  8
#define CDIM   64
#define INNER  512
#define QD     320
#define KD     768
#define ROWS_Q (B_SZ * N_SZ)     // 49152
#define ROWS_K (B_SZ * M_SZ)     // 2560
#define SCALE  0.125f            // 64^-0.5
#define LAMDA1 5.0f

// Scratch (device globals; no allocation allowed)
__device__ float g_q [ROWS_Q * INNER];   // ~100.7 MB
__device__ float g_kp[ROWS_K * INNER];   // ~5.2 MB
__device__ float g_vp[ROWS_K * INNER];   // ~5.2 MB
__device__ float g_ao[ROWS_Q * INNER];   // ~100.7 MB

// ---------------------------------------------------------------------------
// SGEMM: C[r,c] = sum_k A[r,k] * B[c,k] (+ bias[c])
// A: (rows,K) row-major, B: (cols,K) row-major. K % 8 == 0 required.
// 128x128 tile, BK=8, 256 threads, 8x8 micro-tile per thread.
// ---------------------------------------------------------------------------
#define BM 128
#define BN 128
#define BK 8
#define TM 8
#define TN 8

__global__ __launch_bounds__(256, 2)
void sgemm_nt(const float* __restrict__ A, const float* __restrict__ Bm,
              const float* __restrict__ bias, float* __restrict__ C,
              int rows, int cols, int K, int hasBias)
{
    __shared__ __align__(16) float As[BK][BM];
    __shared__ __align__(16) float Bs[BK][BN];

    const int tid  = threadIdx.x;
    const int brow = blockIdx.y * BM;
    const int bcol = blockIdx.x * BN;
    const int tx   = tid & 15;       // 0..15
    const int ty   = tid >> 4;       // 0..15

    float acc[TM][TN];
#pragma unroll
    for (int i = 0; i < TM; i++)
#pragma unroll
        for (int j = 0; j < TN; j++) acc[i][j] = 0.0f;

    const int lrow = tid >> 1;          // 0..127
    const int lk4  = (tid & 1) * 4;     // 0 or 4

    for (int k0 = 0; k0 < K; k0 += BK) {
        // --- load A tile (transposed into As[k][row]) ---
        {
            const int gr = brow + lrow;
            float4 a = make_float4(0.f, 0.f, 0.f, 0.f);
            if (gr < rows)
                a = *(const float4*)(A + (size_t)gr * K + k0 + lk4);
            As[lk4 + 0][lrow] = a.x;
            As[lk4 + 1][lrow] = a.y;
            As[lk4 + 2][lrow] = a.z;
            As[lk4 + 3][lrow] = a.w;
        }
        // --- load B tile ---
        {
            const int gc = bcol + lrow;
            float4 b = make_float4(0.f, 0.f, 0.f, 0.f);
            if (gc < cols)
                b = *(const float4*)(Bm + (size_t)gc * K + k0 + lk4);
            Bs[lk4 + 0][lrow] = b.x;
            Bs[lk4 + 1][lrow] = b.y;
            Bs[lk4 + 2][lrow] = b.z;
            Bs[lk4 + 3][lrow] = b.w;
        }
        __syncthreads();

#pragma unroll
        for (int kk = 0; kk < BK; kk++) {
            float4 a0 = *(const float4*)&As[kk][ty * TM];
            float4 a1 = *(const float4*)&As[kk][ty * TM + 4];
            float4 b0 = *(const float4*)&Bs[kk][tx * TN];
            float4 b1 = *(const float4*)&Bs[kk][tx * TN + 4];
            float af[TM] = {a0.x, a0.y, a0.z, a0.w, a1.x, a1.y, a1.z, a1.w};
            float bf[TN] = {b0.x, b0.y, b0.z, b0.w, b1.x, b1.y, b1.z, b1.w};
#pragma unroll
            for (int i = 0; i < TM; i++)
#pragma unroll
                for (int j = 0; j < TN; j++)
                    acc[i][j] = fmaf(af[i], bf[j], acc[i][j]);
        }
        __syncthreads();
    }

    // --- epilogue ---
#pragma unroll
    for (int i = 0; i < TM; i++) {
        const int r = brow + ty * TM + i;
        if (r >= rows) continue;
#pragma unroll
        for (int j = 0; j < TN; j++) {
            const int c = bcol + tx * TN + j;
            if (c < cols) {
                float v = acc[i][j];
                if (hasBias) v += bias[c];
                C[(size_t)r * cols + c] = v;
            }
        }
    }
}

// ---------------------------------------------------------------------------
// Fused attention: one block per (b, n), one warp per head.
// Phase 1: scores (lane-per-channel-pair, shfl reduce) + mask + box bias
// Phase 2: softmax over M=80 in shared memory
// Phase 3: PV accumulation (coalesced v reads), normalized write
// ---------------------------------------------------------------------------
__global__ __launch_bounds__(256)
void attn_kernel(const float* __restrict__ q,
                 const float* __restrict__ k,
                 const float* __restrict__ v,
                 const int* __restrict__ mask,
                 const float* __restrict__ box,
                 float* __restrict__ out)
{
    const int bn   = blockIdx.x;         // b*N + n
    const int b    = bn / N_SZ;
    const int h    = threadIdx.x >> 5;   // warp id = head
    const int lane = threadIdx.x & 31;

    __shared__ float p_s[HEADS][M_SZ];

    const float* qrow = q + (size_t)bn * INNER + h * CDIM;
    const float  q0 = qrow[lane];
    const float  q1 = qrow[lane + 32];

    const float* kb     = k + (size_t)b * M_SZ * INNER + h * CDIM;
    const float* boxrow = box + (size_t)bn * M_SZ;
    const int*   mrow   = mask + (size_t)b * M_SZ;

    // ---- Phase 1: scores ----
    for (int m = 0; m < M_SZ; m++) {
        const float* kr = kb + (size_t)m * INNER;
        float partial = q0 * kr[lane] + q1 * kr[lane + 32];
#pragma unroll
        for (int off = 16; off > 0; off >>= 1)
            partial += __shfl_xor_sync(0xffffffffu, partial, off);
        if (lane == 0) {
            float s;
            if (mrow[m])
                s = partial * SCALE + LAMDA1 * boxrow[m];
            else
                s = -3.402823466e38f;
            p_s[h][m] = s;
        }
    }
    __syncwarp();

    // ---- Phase 2: softmax over 80 entries ----
    float s0 = p_s[h][lane];
    float s1 = p_s[h][lane + 32];
    float s2 = (lane < 16) ? p_s[h][lane + 64] : -3.402823466e38f;

    float mx = fmaxf(s0, fmaxf(s1, s2));
#pragma unroll
    for (int off = 16; off > 0; off >>= 1)
        mx = fmaxf(mx, __shfl_xor_sync(0xffffffffu, mx, off));

    float e0 = __expf(s0 - mx);
    float e1 = __expf(s1 - mx);
    float e2 = (lane < 16) ? __expf(s2 - mx) : 0.0f;

    float sum = e0 + e1 + e2;
#pragma unroll
    for (int off = 16; off > 0; off >>= 1)
        sum += __shfl_xor_sync(0xffffffffu, sum, off);

    p_s[h][lane]      = e0;
    p_s[h][lane + 32] = e1;
    if (lane < 16) p_s[h][lane + 64] = e2;
    const float inv = 1.0f / sum;
    __syncwarp();

    // ---- Phase 3: PV ----
    const float* vb = v + (size_t)b * M_SZ * INNER + h * CDIM;
    float a0 = 0.0f, a1 = 0.0f;
#pragma unroll 4
    for (int m = 0; m < M_SZ; m++) {
        const float p  = p_s[h][m];
        const float* vr = vb + (size_t)m * INNER;
        a0 = fmaf(p, vr[lane],      a0);
        a1 = fmaf(p, vr[lane + 32], a1);
    }
    out[(size_t)bn * INNER + h * CDIM + lane]      = a0 * inv;
    out[(size_t)bn * INNER + h * CDIM + lane + 32] = a1 * inv;
}

// ---------------------------------------------------------------------------
// Launch
// ---------------------------------------------------------------------------
extern "C" void kernel_launch(void* const* d_in, const int* in_sizes, int n_in,
                              void* d_out, int out_size)
{
    const float* x    = (const float*)d_in[0];
    const float* key  = (const float*)d_in[1];
    const float* val  = (const float*)d_in[2];
    const int*   mask = (const int*)d_in[3];      // bool -> int32 per harness dtypes
    const float* box  = (const float*)d_in[4];
    // d_in[5] = road map: softmax-invariant, unused
    const float* Wq   = (const float*)d_in[6];
    const float* Wk   = (const float*)d_in[7];
    const float* Wv   = (const float*)d_in[8];
    const float* Wo   = (const float*)d_in[9];
    const float* bo   = (const float*)d_in[10];
    float*       out  = (float*)d_out;

    float *q, *kp, *vp, *ao;
    cudaGetSymbolAddress((void**)&q,  g_q);
    cudaGetSymbolAddress((void**)&kp, g_kp);
    cudaGetSymbolAddress((void**)&vp, g_vp);
    cudaGetSymbolAddress((void**)&ao, g_ao);

    dim3 blk(256);

    // 1) Q projection: (49152 x 320) @ (512 x 320)^T -> (49152 x 512)
    {
        dim3 grid((INNER + BN - 1) / BN, (ROWS_Q + BM - 1) / BM);
        sgemm_nt<<<grid, blk>>>(x, Wq, nullptr, q, ROWS_Q, INNER, QD, 0);
    }
    // 2) K projection
    {
        dim3 grid((INNER + BN - 1) / BN, (ROWS_K + BM - 1) / BM);
        sgemm_nt<<<grid, blk>>>(key, Wk, nullptr, kp, ROWS_K, INNER, KD, 0);
    }
    // 3) V projection
    {
        dim3 grid((INNER + BN - 1) / BN, (ROWS_K + BM - 1) / BM);
        sgemm_nt<<<grid, blk>>>(val, Wv, nullptr, vp, ROWS_K, INNER, KD, 0);
    }
    // 4) Attention
    {
        attn_kernel<<<ROWS_Q, 256>>>(q, kp, vp, mask, box, ao);
    }
    // 5) Output projection + bias: (49152 x 512) @ (320 x 512)^T -> (49152 x 320)
    {
        dim3 grid((QD + BN - 1) / BN, (ROWS_Q + BM - 1) / BM);
        sgemm_nt<<<grid, blk>>>(ao, Wo, bo, out, ROWS_Q, QD, INNER, 1);
    }
}

// round 4
// speedup vs baseline: 1.3298x; 1.3298x over previous
#include <cuda_runtime.h>
#include <cuda_bf16.h>
#include <cstdint>

// ---------------------------------------------------------------------------
// CrossAttention via mma.sync bf16 (hi/lo split, 3-pass, fp32 accum).
// tcgen05 is unavailable: harness PTX targets sm_103 (no 'a'), so we use the
// base-target tensor path: mma.sync.m16n8k16 + ldmatrix + cp.async.
// B=32, N=1536, M=80, H=8, C=64, inner=512, QD=320, KD=VD=768
// ---------------------------------------------------------------------------

#define B_SZ   32
#define N_SZ   1536
#define M_SZ   80
#define HEADS  8
#define CDIM   64
#define INNER  512
#define QD     320
#define KD     768
#define ROWS_Q (B_SZ * N_SZ)     // 49152
#define ROWS_K (B_SZ * M_SZ)     // 2560
#define SCALE  0.125f
#define LAMDA1 5.0f

// ---------------- scratch (device globals; allocation forbidden) -----------
__device__ __nv_bfloat16 g_xhi[ROWS_Q * QD],  g_xlo[ROWS_Q * QD];
__device__ __nv_bfloat16 g_khi[ROWS_K * KD],  g_klo[ROWS_K * KD];
__device__ __nv_bfloat16 g_vhi[ROWS_K * KD],  g_vlo[ROWS_K * KD];
__device__ __nv_bfloat16 g_wqhi[INNER * QD],  g_wqlo[INNER * QD];
__device__ __nv_bfloat16 g_wkhi[INNER * KD],  g_wklo[INNER * KD];
__device__ __nv_bfloat16 g_wvhi[INNER * KD],  g_wvlo[INNER * KD];
__device__ __nv_bfloat16 g_wohi[QD * INNER],  g_wolo[QD * INNER];
__device__ float         g_q  [ROWS_Q * INNER];
__device__ float         g_kp [ROWS_K * INNER];
__device__ float         g_vp [ROWS_K * INNER];
__device__ __nv_bfloat16 g_aohi[ROWS_Q * INNER], g_aolo[ROWS_Q * INNER];

// ---------------------------------------------------------------------------
// split: x -> (hi, lo) bf16, hi + lo ~ x with ~2^-17 residual
// ---------------------------------------------------------------------------
__global__ void split_kernel(const float* __restrict__ in,
                             __nv_bfloat16* __restrict__ hi,
                             __nv_bfloat16* __restrict__ lo, int n4)
{
    int i = blockIdx.x * blockDim.x + threadIdx.x;
    if (i >= n4) return;
    float4 v = ((const float4*)in)[i];
    __nv_bfloat16 h0 = __float2bfloat16(v.x);
    __nv_bfloat16 h1 = __float2bfloat16(v.y);
    __nv_bfloat16 h2 = __float2bfloat16(v.z);
    __nv_bfloat16 h3 = __float2bfloat16(v.w);
    ((__nv_bfloat162*)hi)[i * 2 + 0] = __halves2bfloat162(h0, h1);
    ((__nv_bfloat162*)hi)[i * 2 + 1] = __halves2bfloat162(h2, h3);
    ((__nv_bfloat162*)lo)[i * 2 + 0] = __halves2bfloat162(
        __float2bfloat16(v.x - __bfloat162float(h0)),
        __float2bfloat16(v.y - __bfloat162float(h1)));
    ((__nv_bfloat162*)lo)[i * 2 + 1] = __halves2bfloat162(
        __float2bfloat16(v.z - __bfloat162float(h2)),
        __float2bfloat16(v.w - __bfloat162float(h3)));
}

// ---------------------------------------------------------------------------
// mma.sync GEMM: C[r,c] = sum_k A[r,k]*B[c,k] (+bias), hi/lo 3-pass.
// BM=128, BN=128, BK=32, 256 threads (8 warps, 64x32 warp tiles), 3 stages.
// SMEM rows padded to 40 bf16 (80B) -> conflict-free ldmatrix.
// rows % 128 == 0 and K % 32 == 0 required (hold for all calls).
// Column overhang (cols=320) handled by zero-fill cp.async + store guard.
// ---------------------------------------------------------------------------
#define PITCH   40                       // bf16 elems per smem row (80 bytes)
#define STAGE_B (128 * PITCH * 2)        // bytes per operand per stage (10240)
#define KCHUNK  32

__device__ __forceinline__ uint32_t smem_u32(const void* p) {
    uint32_t a;
    asm("{ .reg .u64 t; cvta.to.shared.u64 t, %1; cvt.u32.u64 %0, t; }"
        : "=r"(a) : "l"(p));
    return a;
}
__device__ __forceinline__ void cp_async16(uint32_t dst, const void* src, uint32_t sz) {
    asm volatile("cp.async.cg.shared.global [%0], [%1], 16, %2;"
                 :: "r"(dst), "l"(src), "r"(sz));
}
__device__ __forceinline__ void cp_commit() {
    asm volatile("cp.async.commit_group;");
}
template <int N>
__device__ __forceinline__ void cp_wait() {
    asm volatile("cp.async.wait_group %0;" :: "n"(N));
}
__device__ __forceinline__ void ldmatrix_x4(uint32_t* r, uint32_t addr) {
    asm volatile("ldmatrix.sync.aligned.m8n8.x4.shared.b16 {%0,%1,%2,%3}, [%4];"
                 : "=r"(r[0]), "=r"(r[1]), "=r"(r[2]), "=r"(r[3]) : "r"(addr));
}
__device__ __forceinline__ void ldmatrix_x2(uint32_t* r, uint32_t addr) {
    asm volatile("ldmatrix.sync.aligned.m8n8.x2.shared.b16 {%0,%1}, [%2];"
                 : "=r"(r[0]), "=r"(r[1]) : "r"(addr));
}
__device__ __forceinline__ void mma16816(float* d, const uint32_t* a, const uint32_t* b) {
    asm volatile(
        "mma.sync.aligned.m16n8k16.row.col.f32.bf16.bf16.f32 "
        "{%0,%1,%2,%3}, {%4,%5,%6,%7}, {%8,%9}, {%0,%1,%2,%3};"
        : "+f"(d[0]), "+f"(d[1]), "+f"(d[2]), "+f"(d[3])
        : "r"(a[0]), "r"(a[1]), "r"(a[2]), "r"(a[3]), "r"(b[0]), "r"(b[1]));
}

template <int HAS_BIAS>
__global__ void __launch_bounds__(256, 2)
gemm_mma(const __nv_bfloat16* __restrict__ Ahi, const __nv_bfloat16* __restrict__ Alo,
         const __nv_bfloat16* __restrict__ Bhi, const __nv_bfloat16* __restrict__ Blo,
         const float* __restrict__ bias, float* __restrict__ C,
         int rows, int cols, int K)
{
    extern __shared__ char smem[];
    const uint32_t sbase = smem_u32(smem);

    const int tid  = threadIdx.x;
    const int wid  = tid >> 5;
    const int lane = tid & 31;
    const int wm   = wid >> 2;           // 0..1 -> warp row tile (64 rows)
    const int wn   = wid & 3;            // 0..3 -> warp col tile (32 cols)

    const int rbase = blockIdx.y * 128;
    const int cbase = blockIdx.x * 128;
    const int KC    = K / KCHUNK;
    const int KT    = 3 * KC;

    // cp.async task split: 512 16B chunks per operand per stage, 2/thread
    const int l_row = tid >> 1;                 // 0..127 (2 chunk-pairs)
    // tasks: t in {0,1}: task = t*256 + tid ; row = task>>2 ; ch = task&3
    auto load_stage = [&](int it, int stage) {
        const int seg = it / KC;                // 0:(hi,hi) 1:(hi,lo) 2:(lo,hi)
        const __nv_bfloat16* Ap = (seg == 2) ? Alo : Ahi;
        const __nv_bfloat16* Bp = (seg == 1) ? Blo : Bhi;
        const int kb = (it - seg * KC) * KCHUNK;
        const uint32_t abase = sbase + stage * 2 * STAGE_B;
        const uint32_t bbase = abase + STAGE_B;
#pragma unroll
        for (int t = 0; t < 2; t++) {
            const int task = t * 256 + tid;
            const int row  = task >> 2;
            const int ch   = task & 3;
            // A: rows always in range (rows % 128 == 0)
            cp_async16(abase + row * 80 + ch * 16,
                       Ap + (size_t)(rbase + row) * K + kb + ch * 8, 16);
            // B: guard column overhang with zero-fill
            const int col   = cbase + row;
            const int valid = (col < cols);
            cp_async16(bbase + row * 80 + ch * 16,
                       Bp + (size_t)(valid ? col : 0) * K + kb + ch * 8,
                       valid ? 16u : 0u);
        }
        cp_commit();
    };

    float acc[4][4][4];
#pragma unroll
    for (int i = 0; i < 4; i++)
#pragma unroll
        for (int j = 0; j < 4; j++)
#pragma unroll
            for (int e = 0; e < 4; e++) acc[i][j][e] = 0.0f;

    load_stage(0, 0);
    load_stage(1, 1);

    // per-lane ldmatrix address components
    const int g   = lane >> 3;            // 0..3
    const int r8  = lane & 7;
    // A (x4): row = wm*64 + i*16 + (g&1)*8 + r8 ; kbyte = (g>>1)*16 + s*32
    const int a_row_off = (g & 1) * 8 + r8;
    const int a_k_off   = (g >> 1) * 16;
    // B (x2): row = wn*32 + j*8 + r8 ; kbyte = (g&1)*16 + s*32 (lanes 16-31 dup)
    const int b_row_off = r8;
    const int b_k_off   = (g & 1) * 16;

    for (int it = 0; it < KT; it++) {
        cp_wait<1>();
        __syncthreads();
        if (it + 2 < KT) load_stage(it + 2, (it + 2) % 3);
        else cp_commit();

        const int stage = it % 3;
        const uint32_t sA = sbase + stage * 2 * STAGE_B;
        const uint32_t sB = sA + STAGE_B;

#pragma unroll
        for (int s = 0; s < 2; s++) {
            uint32_t afrag[4][4];
            uint32_t bfrag[4][2];
#pragma unroll
            for (int i = 0; i < 4; i++)
                ldmatrix_x4(afrag[i],
                    sA + (wm * 64 + i * 16 + a_row_off) * 80 + a_k_off + s * 32);
#pragma unroll
            for (int j = 0; j < 4; j++)
                ldmatrix_x2(bfrag[j],
                    sB + (wn * 32 + j * 8 + b_row_off) * 80 + b_k_off + s * 32);
#pragma unroll
            for (int i = 0; i < 4; i++)
#pragma unroll
                for (int j = 0; j < 4; j++)
                    mma16816(acc[i][j], afrag[i], bfrag[j]);
        }
        __syncthreads();
    }

    // epilogue: direct register -> global stores (float2)
    const int qrow = lane >> 2;           // 0..7
    const int qcol = (lane & 3) * 2;
#pragma unroll
    for (int i = 0; i < 4; i++) {
        const int row0 = rbase + wm * 64 + i * 16 + qrow;
#pragma unroll
        for (int j = 0; j < 4; j++) {
            const int col0 = cbase + wn * 32 + j * 8 + qcol;
            if (col0 >= cols) continue;
            float b0 = 0.f, b1 = 0.f;
            if (HAS_BIAS) { b0 = bias[col0]; b1 = bias[col0 + 1]; }
            *(float2*)(C + (size_t)row0 * cols + col0) =
                make_float2(acc[i][j][0] + b0, acc[i][j][1] + b1);
            *(float2*)(C + (size_t)(row0 + 8) * cols + col0) =
                make_float2(acc[i][j][2] + b0, acc[i][j][3] + b1);
        }
    }
}

// ---------------------------------------------------------------------------
// Fused attention (known-correct from R2); epilogue emits hi/lo split of ao.
// ---------------------------------------------------------------------------
__global__ __launch_bounds__(256)
void attn_kernel(const float* __restrict__ q,
                 const float* __restrict__ k,
                 const float* __restrict__ v,
                 const int* __restrict__ mask,
                 const float* __restrict__ box,
                 __nv_bfloat16* __restrict__ aohi,
                 __nv_bfloat16* __restrict__ aolo)
{
    const int bn   = blockIdx.x;
    const int b    = bn / N_SZ;
    const int h    = threadIdx.x >> 5;
    const int lane = threadIdx.x & 31;

    __shared__ float p_s[HEADS][M_SZ];

    const float* qrow = q + (size_t)bn * INNER + h * CDIM;
    const float  q0 = qrow[lane];
    const float  q1 = qrow[lane + 32];

    const float* kb     = k + (size_t)b * M_SZ * INNER + h * CDIM;
    const float* boxrow = box + (size_t)bn * M_SZ;
    const int*   mrow   = mask + (size_t)b * M_SZ;

    for (int m = 0; m < M_SZ; m++) {
        const float* kr = kb + (size_t)m * INNER;
        float partial = q0 * kr[lane] + q1 * kr[lane + 32];
#pragma unroll
        for (int off = 16; off > 0; off >>= 1)
            partial += __shfl_xor_sync(0xffffffffu, partial, off);
        if (lane == 0)
            p_s[h][m] = mrow[m] ? (partial * SCALE + LAMDA1 * boxrow[m])
                                : -3.402823466e38f;
    }
    __syncwarp();

    float s0 = p_s[h][lane];
    float s1 = p_s[h][lane + 32];
    float s2 = (lane < 16) ? p_s[h][lane + 64] : -3.402823466e38f;

    float mx = fmaxf(s0, fmaxf(s1, s2));
#pragma unroll
    for (int off = 16; off > 0; off >>= 1)
        mx = fmaxf(mx, __shfl_xor_sync(0xffffffffu, mx, off));

    float e0 = __expf(s0 - mx);
    float e1 = __expf(s1 - mx);
    float e2 = (lane < 16) ? __expf(s2 - mx) : 0.0f;

    float sum = e0 + e1 + e2;
#pragma unroll
    for (int off = 16; off > 0; off >>= 1)
        sum += __shfl_xor_sync(0xffffffffu, sum, off);

    p_s[h][lane]      = e0;
    p_s[h][lane + 32] = e1;
    if (lane < 16) p_s[h][lane + 64] = e2;
    const float inv = 1.0f / sum;
    __syncwarp();

    const float* vb = v + (size_t)b * M_SZ * INNER + h * CDIM;
    float a0 = 0.0f, a1 = 0.0f;
#pragma unroll 4
    for (int m = 0; m < M_SZ; m++) {
        const float p  = p_s[h][m];
        const float* vr = vb + (size_t)m * INNER;
        a0 = fmaf(p, vr[lane],      a0);
        a1 = fmaf(p, vr[lane + 32], a1);
    }
    const float o0 = a0 * inv, o1 = a1 * inv;
    const size_t i0 = (size_t)bn * INNER + h * CDIM + lane;
    __nv_bfloat16 h0 = __float2bfloat16(o0);
    __nv_bfloat16 h1 = __float2bfloat16(o1);
    aohi[i0]      = h0;
    aohi[i0 + 32] = h1;
    aolo[i0]      = __float2bfloat16(o0 - __bfloat162float(h0));
    aolo[i0 + 32] = __float2bfloat16(o1 - __bfloat162float(h1));
}

// ---------------------------------------------------------------------------
// Launch
// ---------------------------------------------------------------------------
extern "C" void kernel_launch(void* const* d_in, const int* in_sizes, int n_in,
                              void* d_out, int out_size)
{
    const float* x    = (const float*)d_in[0];
    const float* key  = (const float*)d_in[1];
    const float* val  = (const float*)d_in[2];
    const int*   mask = (const int*)d_in[3];
    const float* box  = (const float*)d_in[4];
    // d_in[5] road map: softmax-invariant, unused
    const float* Wq   = (const float*)d_in[6];
    const float* Wk   = (const float*)d_in[7];
    const float* Wv   = (const float*)d_in[8];
    const float* Wo   = (const float*)d_in[9];
    const float* bo   = (const float*)d_in[10];
    float*       out  = (float*)d_out;

    __nv_bfloat16 *xhi, *xlo, *khi, *klo, *vhi, *vlo;
    __nv_bfloat16 *wqhi, *wqlo, *wkhi, *wklo, *wvhi, *wvlo, *wohi, *wolo;
    __nv_bfloat16 *aohi, *aolo;
    float *q, *kp, *vp;
    cudaGetSymbolAddress((void**)&xhi, g_xhi);   cudaGetSymbolAddress((void**)&xlo, g_xlo);
    cudaGetSymbolAddress((void**)&khi, g_khi);   cudaGetSymbolAddress((void**)&klo, g_klo);
    cudaGetSymbolAddress((void**)&vhi, g_vhi);   cudaGetSymbolAddress((void**)&vlo, g_vlo);
    cudaGetSymbolAddress((void**)&wqhi, g_wqhi); cudaGetSymbolAddress((void**)&wqlo, g_wqlo);
    cudaGetSymbolAddress((void**)&wkhi, g_wkhi); cudaGetSymbolAddress((void**)&wklo, g_wklo);
    cudaGetSymbolAddress((void**)&wvhi, g_wvhi); cudaGetSymbolAddress((void**)&wvlo, g_wvlo);
    cudaGetSymbolAddress((void**)&wohi, g_wohi); cudaGetSymbolAddress((void**)&wolo, g_wolo);
    cudaGetSymbolAddress((void**)&aohi, g_aohi); cudaGetSymbolAddress((void**)&aolo, g_aolo);
    cudaGetSymbolAddress((void**)&q,  g_q);
    cudaGetSymbolAddress((void**)&kp, g_kp);
    cudaGetSymbolAddress((void**)&vp, g_vp);

    constexpr int SMEM = 3 * 2 * STAGE_B;  // 61440 bytes
    cudaFuncSetAttribute(gemm_mma<0>, cudaFuncAttributeMaxDynamicSharedMemorySize, SMEM);
    cudaFuncSetAttribute(gemm_mma<1>, cudaFuncAttributeMaxDynamicSharedMemorySize, SMEM);

    // ---- splits ----
    auto split = [&](const float* src, __nv_bfloat16* h, __nv_bfloat16* l, int n) {
        int n4 = n / 4;
        split_kernel<<<(n4 + 255) / 256, 256>>>(src, h, l, n4);
    };
    split(x,   xhi, xlo, ROWS_Q * QD);
    split(key, khi, klo, ROWS_K * KD);
    split(val, vhi, vlo, ROWS_K * KD);
    split(Wq,  wqhi, wqlo, INNER * QD);
    split(Wk,  wkhi, wklo, INNER * KD);
    split(Wv,  wvhi, wvlo, INNER * KD);
    split(Wo,  wohi, wolo, QD * INNER);

    // ---- projections on tensor cores (mma.sync) ----
    gemm_mma<0><<<dim3(INNER / 128, ROWS_Q / 128), 256, SMEM>>>(
        xhi, xlo, wqhi, wqlo, nullptr, q, ROWS_Q, INNER, QD);
    gemm_mma<0><<<dim3(INNER / 128, ROWS_K / 128), 256, SMEM>>>(
        khi, klo, wkhi, wklo, nullptr, kp, ROWS_K, INNER, KD);
    gemm_mma<0><<<dim3(INNER / 128, ROWS_K / 128), 256, SMEM>>>(
        vhi, vlo, wvhi, wvlo, nullptr, vp, ROWS_K, INNER, KD);

    // ---- attention ----
    attn_kernel<<<ROWS_Q, 256>>>(q, kp, vp, mask, box, aohi, aolo);

    // ---- output projection + bias (cols=320 -> 3 col tiles, last partial) ----
    gemm_mma<1><<<dim3((QD + 127) / 128, ROWS_Q / 128), 256, SMEM>>>(
        aohi, aolo, wohi, wolo, bo, out, ROWS_Q, QD, INNER);
}

// round 5
// speedup vs baseline: 3.9161x; 2.9449x over previous
#include <cuda_runtime.h>
#include <cuda_bf16.h>
#include <cstdint>

// ---------------------------------------------------------------------------
// CrossAttention, fully tensor-core (mma.sync bf16 hi/lo split, fp32 accum).
//   1) q  = x @ Wq^T      -> bf16 hi/lo        (gemm_mma MODE 2)
//   2) kp = key @ Wk^T    -> bf16 hi/lo        (gemm_mma MODE 2)
//   3) vt = (val @ Wv^T)^T per head -> hi/lo   (gemm_mma MODE 3)
//   4) S = QK^T + mask/bias, softmax fused     (bgemm_qk) -> P bf16 hi/lo
//   5) ao = P V                                 (bgemm_pv) -> bf16 hi/lo
//   6) out = ao @ Wo^T + bo                    (gemm_mma MODE 1, fp32)
// road bias constant over key axis -> softmax-invariant -> dropped.
// ---------------------------------------------------------------------------

#define B_SZ   32
#define N_SZ   1536
#define M_SZ   80
#define HEADS  8
#define CDIM   64
#define INNER  512
#define QD     320
#define KD     768
#define ROWS_Q (B_SZ * N_SZ)     // 49152
#define ROWS_K (B_SZ * M_SZ)     // 2560
#define SCALE  0.125f
#define LAMDA1 5.0f
#define BIGNEG (-3.402823466e38f)

// ---------------- scratch (device globals; allocation forbidden) -----------
__device__ __nv_bfloat16 g_xhi[ROWS_Q * QD],  g_xlo[ROWS_Q * QD];
__device__ __nv_bfloat16 g_khi[ROWS_K * KD],  g_klo[ROWS_K * KD];
__device__ __nv_bfloat16 g_vhi[ROWS_K * KD],  g_vlo[ROWS_K * KD];
__device__ __nv_bfloat16 g_wqhi[INNER * QD],  g_wqlo[INNER * QD];
__device__ __nv_bfloat16 g_wkhi[INNER * KD],  g_wklo[INNER * KD];
__device__ __nv_bfloat16 g_wvhi[INNER * KD],  g_wvlo[INNER * KD];
__device__ __nv_bfloat16 g_wohi[QD * INNER],  g_wolo[QD * INNER];
__device__ __nv_bfloat16 g_qhi [ROWS_Q * INNER], g_qlo [ROWS_Q * INNER];
__device__ __nv_bfloat16 g_kphi[ROWS_K * INNER], g_kplo[ROWS_K * INNER];
__device__ __nv_bfloat16 g_vthi[ROWS_K * INNER], g_vtlo[ROWS_K * INNER]; // [bh][c][m]
__device__ __nv_bfloat16 g_phi [B_SZ * HEADS * N_SZ * M_SZ];
__device__ __nv_bfloat16 g_plo [B_SZ * HEADS * N_SZ * M_SZ];
__device__ __nv_bfloat16 g_aohi[ROWS_Q * INNER], g_aolo[ROWS_Q * INNER];

// ---------------------------------------------------------------------------
// primitives
// ---------------------------------------------------------------------------
__device__ __forceinline__ uint32_t smem_u32(const void* p) {
    uint32_t a;
    asm("{ .reg .u64 t; cvta.to.shared.u64 t, %1; cvt.u32.u64 %0, t; }"
        : "=r"(a) : "l"(p));
    return a;
}
__device__ __forceinline__ void cp_async16(uint32_t dst, const void* src, uint32_t sz) {
    asm volatile("cp.async.cg.shared.global [%0], [%1], 16, %2;"
                 :: "r"(dst), "l"(src), "r"(sz));
}
__device__ __forceinline__ void cp_commit() { asm volatile("cp.async.commit_group;"); }
template <int N>
__device__ __forceinline__ void cp_wait() {
    asm volatile("cp.async.wait_group %0;" :: "n"(N));
}
__device__ __forceinline__ void ldmatrix_x4(uint32_t* r, uint32_t addr) {
    asm volatile("ldmatrix.sync.aligned.m8n8.x4.shared.b16 {%0,%1,%2,%3}, [%4];"
                 : "=r"(r[0]), "=r"(r[1]), "=r"(r[2]), "=r"(r[3]) : "r"(addr));
}
__device__ __forceinline__ void ldmatrix_x2(uint32_t* r, uint32_t addr) {
    asm volatile("ldmatrix.sync.aligned.m8n8.x2.shared.b16 {%0,%1}, [%2];"
                 : "=r"(r[0]), "=r"(r[1]) : "r"(addr));
}
__device__ __forceinline__ void mma16816(float* d, const uint32_t* a, const uint32_t* b) {
    asm volatile(
        "mma.sync.aligned.m16n8k16.row.col.f32.bf16.bf16.f32 "
        "{%0,%1,%2,%3}, {%4,%5,%6,%7}, {%8,%9}, {%0,%1,%2,%3};"
        : "+f"(d[0]), "+f"(d[1]), "+f"(d[2]), "+f"(d[3])
        : "r"(a[0]), "r"(a[1]), "r"(a[2]), "r"(a[3]), "r"(b[0]), "r"(b[1]));
}
__device__ __forceinline__ void split_store2(__nv_bfloat16* hi, __nv_bfloat16* lo,
                                             size_t idx, float v0, float v1) {
    __nv_bfloat16 h0 = __float2bfloat16(v0);
    __nv_bfloat16 h1 = __float2bfloat16(v1);
    *(__nv_bfloat162*)(hi + idx) = __halves2bfloat162(h0, h1);
    *(__nv_bfloat162*)(lo + idx) = __halves2bfloat162(
        __float2bfloat16(v0 - __bfloat162float(h0)),
        __float2bfloat16(v1 - __bfloat162float(h1)));
}

// ---------------------------------------------------------------------------
// split: fp32 -> (hi, lo) bf16
// ---------------------------------------------------------------------------
__global__ void split_kernel(const float* __restrict__ in,
                             __nv_bfloat16* __restrict__ hi,
                             __nv_bfloat16* __restrict__ lo, int n4)
{
    int i = blockIdx.x * blockDim.x + threadIdx.x;
    if (i >= n4) return;
    float4 v = ((const float4*)in)[i];
    split_store2(hi, lo, (size_t)i * 4,     v.x, v.y);
    split_store2(hi, lo, (size_t)i * 4 + 2, v.z, v.w);
}

// ---------------------------------------------------------------------------
// main GEMM (validated R4 core): C[r,c] = sum_k A[r,k]*B[c,k], hi/lo 3-pass.
// MODE 0: fp32 out; 1: fp32 + bias; 2: bf16 hi/lo out; 3: per-head-transposed
// bf16 hi/lo out for V (vt[(b*8+h)*64+c][m]).
// ---------------------------------------------------------------------------
#define STAGE_B (128 * 40 * 2)   // 10240 bytes per operand per stage
#define KCHUNK  32

template <int MODE>
__global__ void __launch_bounds__(256, 2)
gemm_mma(const __nv_bfloat16* __restrict__ Ahi, const __nv_bfloat16* __restrict__ Alo,
         const __nv_bfloat16* __restrict__ Bhi, const __nv_bfloat16* __restrict__ Blo,
         const float* __restrict__ bias, float* __restrict__ Cf,
         __nv_bfloat16* __restrict__ Chi, __nv_bfloat16* __restrict__ Clo,
         int rows, int cols, int K)
{
    extern __shared__ char smem[];
    const uint32_t sbase = smem_u32(smem);

    const int tid  = threadIdx.x;
    const int wid  = tid >> 5;
    const int lane = tid & 31;
    const int wm   = wid >> 2;
    const int wn   = wid & 3;

    const int rbase = blockIdx.y * 128;
    const int cbase = blockIdx.x * 128;
    const int KC    = K / KCHUNK;
    const int KT    = 3 * KC;

    auto load_stage = [&](int it, int stage) {
        const int seg = it / KC;
        const __nv_bfloat16* Ap = (seg == 2) ? Alo : Ahi;
        const __nv_bfloat16* Bp = (seg == 1) ? Blo : Bhi;
        const int kb = (it - seg * KC) * KCHUNK;
        const uint32_t abase = sbase + stage * 2 * STAGE_B;
        const uint32_t bbase = abase + STAGE_B;
#pragma unroll
        for (int t = 0; t < 2; t++) {
            const int task = t * 256 + tid;
            const int row  = task >> 2;
            const int ch   = task & 3;
            cp_async16(abase + row * 80 + ch * 16,
                       Ap + (size_t)(rbase + row) * K + kb + ch * 8, 16);
            const int col   = cbase + row;
            const int valid = (col < cols);
            cp_async16(bbase + row * 80 + ch * 16,
                       Bp + (size_t)(valid ? col : 0) * K + kb + ch * 8,
                       valid ? 16u : 0u);
        }
        cp_commit();
    };

    float acc[4][4][4];
#pragma unroll
    for (int i = 0; i < 4; i++)
#pragma unroll
        for (int j = 0; j < 4; j++)
#pragma unroll
            for (int e = 0; e < 4; e++) acc[i][j][e] = 0.0f;

    load_stage(0, 0);
    load_stage(1, 1);

    const int g  = lane >> 3;
    const int r8 = lane & 7;
    const int a_row_off = (g & 1) * 8 + r8;
    const int a_k_off   = (g >> 1) * 16;
    const int b_row_off = r8;
    const int b_k_off   = (g & 1) * 16;

    for (int it = 0; it < KT; it++) {
        cp_wait<1>();
        __syncthreads();
        if (it + 2 < KT) load_stage(it + 2, (it + 2) % 3);
        else cp_commit();

        const int stage = it % 3;
        const uint32_t sA = sbase + stage * 2 * STAGE_B;
        const uint32_t sB = sA + STAGE_B;

#pragma unroll
        for (int s = 0; s < 2; s++) {
            uint32_t afrag[4][4];
            uint32_t bfrag[4][2];
#pragma unroll
            for (int i = 0; i < 4; i++)
                ldmatrix_x4(afrag[i],
                    sA + (wm * 64 + i * 16 + a_row_off) * 80 + a_k_off + s * 32);
#pragma unroll
            for (int j = 0; j < 4; j++)
                ldmatrix_x2(bfrag[j],
                    sB + (wn * 32 + j * 8 + b_row_off) * 80 + b_k_off + s * 32);
#pragma unroll
            for (int i = 0; i < 4; i++)
#pragma unroll
                for (int j = 0; j < 4; j++)
                    mma16816(acc[i][j], afrag[i], bfrag[j]);
        }
        __syncthreads();
    }

    const int qrow = lane >> 2;
    const int qcol = (lane & 3) * 2;
#pragma unroll
    for (int i = 0; i < 4; i++) {
        const int row0 = rbase + wm * 64 + i * 16 + qrow;
#pragma unroll
        for (int j = 0; j < 4; j++) {
            const int col0 = cbase + wn * 32 + j * 8 + qcol;
            if (col0 >= cols) continue;
            if (MODE <= 1) {
                float b0 = 0.f, b1 = 0.f;
                if (MODE == 1) { b0 = bias[col0]; b1 = bias[col0 + 1]; }
                *(float2*)(Cf + (size_t)row0 * cols + col0) =
                    make_float2(acc[i][j][0] + b0, acc[i][j][1] + b1);
                *(float2*)(Cf + (size_t)(row0 + 8) * cols + col0) =
                    make_float2(acc[i][j][2] + b0, acc[i][j][3] + b1);
            } else if (MODE == 2) {
                split_store2(Chi, Clo, (size_t)row0 * cols + col0,
                             acc[i][j][0], acc[i][j][1]);
                split_store2(Chi, Clo, (size_t)(row0 + 8) * cols + col0,
                             acc[i][j][2], acc[i][j][3]);
            } else { // MODE 3: vt[(b*8 + col/64)*64 + col%64][m], row=(b*80+m)
#pragma unroll
                for (int rr = 0; rr < 2; rr++) {
                    const int r = row0 + rr * 8;
                    const int bb = r / M_SZ;
                    const int m  = r - bb * M_SZ;
#pragma unroll
                    for (int cc = 0; cc < 2; cc++) {
                        const int col = col0 + cc;
                        const int idx = (bb * HEADS + (col >> 6)) * CDIM + (col & 63);
                        const float v = acc[i][j][rr * 2 + cc];
                        __nv_bfloat16 h = __float2bfloat16(v);
                        Chi[(size_t)idx * M_SZ + m] = h;
                        Clo[(size_t)idx * M_SZ + m] =
                            __float2bfloat16(v - __bfloat162float(h));
                    }
                }
            }
        }
    }
}

// ---------------------------------------------------------------------------
// bgemm_qk: per (b,h,ntile): S[128x80] = Q·K^T (hi/lo 3-pass), fused
// mask/bias/softmax, emits normalized P as bf16 hi/lo. Q/K pitch 72 bf16.
// ---------------------------------------------------------------------------
#define QK_PITCH 144                      // bytes per smem row (72 bf16)
#define QK_QBUF  (128 * QK_PITCH)         // 18432
#define QK_KBUF  (80 * QK_PITCH)          // 11520

__global__ void __launch_bounds__(256)
bgemm_qk(const __nv_bfloat16* __restrict__ qhi, const __nv_bfloat16* __restrict__ qlo,
         const __nv_bfloat16* __restrict__ khi, const __nv_bfloat16* __restrict__ klo,
         const int* __restrict__ mask, const float* __restrict__ box,
         __nv_bfloat16* __restrict__ phi, __nv_bfloat16* __restrict__ plo)
{
    extern __shared__ char smem[];
    const uint32_t sbase = smem_u32(smem);
    const int tid  = threadIdx.x;
    const int wid  = tid >> 5;
    const int lane = tid & 31;
    const int bh   = blockIdx.y;
    const int b    = bh >> 3, h = bh & 7;
    const int nbase = blockIdx.x * 128;

    const uint32_t sQ = sbase;
    const uint32_t sK = sbase + 2 * QK_QBUF;

    const __nv_bfloat16* qsrc[2] = {qhi, qlo};
#pragma unroll
    for (int u = 0; u < 8; u++) {          // 2048 Q chunks
        const int task = u * 256 + tid;
        const int buf  = task >> 10;
        const int rem  = task & 1023;
        const int row  = rem >> 3, ch = rem & 7;
        cp_async16(sQ + buf * QK_QBUF + row * QK_PITCH + ch * 16,
                   qsrc[buf] + (size_t)(b * N_SZ + nbase + row) * INNER + h * CDIM + ch * 8, 16);
    }
    const __nv_bfloat16* ksrc[2] = {khi, klo};
#pragma unroll
    for (int u = 0; u < 5; u++) {          // 1280 K chunks
        const int task = u * 256 + tid;
        const int buf  = task >= 640;
        const int rem  = task - buf * 640;
        const int row  = rem >> 3, ch = rem & 7;
        cp_async16(sK + buf * QK_KBUF + row * QK_PITCH + ch * 16,
                   ksrc[buf] + (size_t)(b * M_SZ + row) * INNER + h * CDIM + ch * 8, 16);
    }
    cp_commit();
    cp_wait<0>();
    __syncthreads();

    const int wr = wid >> 1, wc = wid & 1;   // 4 x 2 warps: 32 rows x 40 cols
    const int g  = lane >> 3, r8 = lane & 7;
    const int a_row_off = (g & 1) * 8 + r8;
    const int a_k_off   = (g >> 1) * 16;
    const int b_row_off = r8;
    const int b_k_off   = (g & 1) * 16;

    float acc[2][5][4];
#pragma unroll
    for (int i = 0; i < 2; i++)
#pragma unroll
        for (int j = 0; j < 5; j++)
#pragma unroll
            for (int e = 0; e < 4; e++) acc[i][j][e] = 0.0f;

#pragma unroll
    for (int p = 0; p < 3; p++) {            // (h,h), (h,l), (l,h)
        const uint32_t qb = sQ + ((p == 2) ? QK_QBUF : 0);
        const uint32_t kb = sK + ((p == 1) ? QK_KBUF : 0);
#pragma unroll
        for (int ks = 0; ks < 4; ks++) {
            uint32_t af[2][4], bf[5][2];
#pragma unroll
            for (int i = 0; i < 2; i++)
                ldmatrix_x4(af[i], qb + (wr * 32 + i * 16 + a_row_off) * QK_PITCH
                                      + ks * 32 + a_k_off);
#pragma unroll
            for (int j = 0; j < 5; j++)
                ldmatrix_x2(bf[j], kb + (wc * 40 + j * 8 + b_row_off) * QK_PITCH
                                      + ks * 32 + b_k_off);
#pragma unroll
            for (int i = 0; i < 2; i++)
#pragma unroll
                for (int j = 0; j < 5; j++)
                    mma16816(acc[i][j], af[i], bf[j]);
        }
    }
    __syncthreads();   // done with Q/K smem; reuse as S

    float* sS = (float*)smem;                 // [128][88] fp32 = 45056 B
    const int qrow = lane >> 2;
    const int qcol = (lane & 3) * 2;
#pragma unroll
    for (int i = 0; i < 2; i++) {
        const int r0 = wr * 32 + i * 16 + qrow;
#pragma unroll
        for (int j = 0; j < 5; j++) {
            const int c0 = wc * 40 + j * 8 + qcol;
            *(float2*)&sS[r0 * 88 + c0]       = make_float2(acc[i][j][0], acc[i][j][1]);
            *(float2*)&sS[(r0 + 8) * 88 + c0] = make_float2(acc[i][j][2], acc[i][j][3]);
        }
    }
    __syncthreads();

    // softmax: warp handles 16 rows; lane covers m = lane, lane+32, lane+64(<16)
    const int* mrow = mask + b * M_SZ;
    const int m_ok0 = mrow[lane];
    const int m_ok1 = mrow[lane + 32];
    const int m_ok2 = (lane < 16) ? mrow[lane + 64] : 0;

    for (int rr = 0; rr < 16; rr++) {
        const int row = wid * 16 + rr;
        const int n   = nbase + row;
        const float* boxrow = box + (size_t)(b * N_SZ + n) * M_SZ;

        float s0 = m_ok0 ? sS[row * 88 + lane]      * SCALE + LAMDA1 * boxrow[lane]      : BIGNEG;
        float s1 = m_ok1 ? sS[row * 88 + lane + 32] * SCALE + LAMDA1 * boxrow[lane + 32] : BIGNEG;
        float s2 = m_ok2 ? sS[row * 88 + lane + 64] * SCALE + LAMDA1 * boxrow[lane + 64] : BIGNEG;

        float mx = fmaxf(s0, fmaxf(s1, s2));
#pragma unroll
        for (int off = 16; off > 0; off >>= 1)
            mx = fmaxf(mx, __shfl_xor_sync(0xffffffffu, mx, off));

        float e0 = __expf(s0 - mx);
        float e1 = __expf(s1 - mx);
        float e2 = (lane < 16) ? __expf(s2 - mx) : 0.0f;

        float sum = e0 + e1 + e2;
#pragma unroll
        for (int off = 16; off > 0; off >>= 1)
            sum += __shfl_xor_sync(0xffffffffu, sum, off);
        const float inv = 1.0f / sum;

        const size_t base = ((size_t)bh * N_SZ + n) * M_SZ;
        const float p0 = e0 * inv, p1 = e1 * inv;
        __nv_bfloat16 h0 = __float2bfloat16(p0);
        __nv_bfloat16 h1 = __float2bfloat16(p1);
        phi[base + lane]      = h0;
        phi[base + lane + 32] = h1;
        plo[base + lane]      = __float2bfloat16(p0 - __bfloat162float(h0));
        plo[base + lane + 32] = __float2bfloat16(p1 - __bfloat162float(h1));
        if (lane < 16) {
            const float p2 = e2 * inv;
            __nv_bfloat16 h2 = __float2bfloat16(p2);
            phi[base + lane + 64] = h2;
            plo[base + lane + 64] = __float2bfloat16(p2 - __bfloat162float(h2));
        }
    }
}

// ---------------------------------------------------------------------------
// bgemm_pv: per (b,h,ntile): O[128x64] = P[128x80] · Vt^T (hi/lo 3-pass),
// emits ao bf16 hi/lo. P/Vt pitch 88 bf16 (176B).
// ---------------------------------------------------------------------------
#define PV_PITCH 176
#define PV_PBUF  (128 * PV_PITCH)         // 22528
#define PV_VBUF  (64 * PV_PITCH)          // 11264

__global__ void __launch_bounds__(256)
bgemm_pv(const __nv_bfloat16* __restrict__ phi, const __nv_bfloat16* __restrict__ plo,
         const __nv_bfloat16* __restrict__ vthi, const __nv_bfloat16* __restrict__ vtlo,
         __nv_bfloat16* __restrict__ aohi, __nv_bfloat16* __restrict__ aolo)
{
    extern __shared__ char smem[];
    const uint32_t sbase = smem_u32(smem);
    const int tid  = threadIdx.x;
    const int wid  = tid >> 5;
    const int lane = tid & 31;
    const int bh   = blockIdx.y;
    const int b    = bh >> 3, h = bh & 7;
    const int nbase = blockIdx.x * 128;

    const uint32_t sP = sbase;
    const uint32_t sV = sbase + 2 * PV_PBUF;

    const __nv_bfloat16* psrc[2] = {phi, plo};
#pragma unroll
    for (int u = 0; u < 10; u++) {          // 2560 P chunks (10 x 16B per row)
        const int task = u * 256 + tid;
        const int buf  = task >= 1280;
        const int rem  = task - buf * 1280;
        const int row  = rem / 10, ch = rem - row * 10;
        cp_async16(sP + buf * PV_PBUF + row * PV_PITCH + ch * 16,
                   psrc[buf] + ((size_t)bh * N_SZ + nbase + row) * M_SZ + ch * 8, 16);
    }
    const __nv_bfloat16* vsrc[2] = {vthi, vtlo};
#pragma unroll
    for (int u = 0; u < 5; u++) {           // 1280 Vt chunks
        const int task = u * 256 + tid;
        const int buf  = task >= 640;
        const int rem  = task - buf * 640;
        const int row  = rem / 10, ch = rem - row * 10;
        cp_async16(sV + buf * PV_VBUF + row * PV_PITCH + ch * 16,
                   vsrc[buf] + ((size_t)bh * CDIM + row) * M_SZ + ch * 8, 16);
    }
    cp_commit();
    cp_wait<0>();
    __syncthreads();

    const int wr = wid >> 1, wc = wid & 1;   // 4 x 2 warps: 32 rows x 32 cols
    const int g  = lane >> 3, r8 = lane & 7;
    const int a_row_off = (g & 1) * 8 + r8;
    const int a_k_off   = (g >> 1) * 16;
    const int b_row_off = r8;
    const int b_k_off   = (g & 1) * 16;

    float acc[2][4][4];
#pragma unroll
    for (int i = 0; i < 2; i++)
#pragma unroll
        for (int j = 0; j < 4; j++)
#pragma unroll
            for (int e = 0; e < 4; e++) acc[i][j][e] = 0.0f;

#pragma unroll
    for (int p = 0; p < 3; p++) {            // (Ph,Vh), (Ph,Vl), (Pl,Vh)
        const uint32_t pb = sP + ((p == 2) ? PV_PBUF : 0);
        const uint32_t vb = sV + ((p == 1) ? PV_VBUF : 0);
#pragma unroll
        for (int ks = 0; ks < 5; ks++) {     // K = 80 = 5 x 16
            uint32_t af[2][4], bf[4][2];
#pragma unroll
            for (int i = 0; i < 2; i++)
                ldmatrix_x4(af[i], pb + (wr * 32 + i * 16 + a_row_off) * PV_PITCH
                                      + ks * 32 + a_k_off);
#pragma unroll
            for (int j = 0; j < 4; j++)
                ldmatrix_x2(bf[j], vb + (wc * 32 + j * 8 + b_row_off) * PV_PITCH
                                      + ks * 32 + b_k_off);
#pragma unroll
            for (int i = 0; i < 2; i++)
#pragma unroll
                for (int j = 0; j < 4; j++)
                    mma16816(acc[i][j], af[i], bf[j]);
        }
    }

    const int qrow = lane >> 2;
    const int qcol = (lane & 3) * 2;
#pragma unroll
    for (int i = 0; i < 2; i++) {
        const int n0 = nbase + wr * 32 + i * 16 + qrow;
#pragma unroll
        for (int j = 0; j < 4; j++) {
            const int c0 = wc * 32 + j * 8 + qcol;
            const size_t i0 = ((size_t)(b * N_SZ + n0)) * INNER + h * CDIM + c0;
            split_store2(aohi, aolo, i0,               acc[i][j][0], acc[i][j][1]);
            split_store2(aohi, aolo, i0 + 8 * INNER,   acc[i][j][2], acc[i][j][3]);
        }
    }
}

// ---------------------------------------------------------------------------
// Launch
// ---------------------------------------------------------------------------
extern "C" void kernel_launch(void* const* d_in, const int* in_sizes, int n_in,
                              void* d_out, int out_size)
{
    const float* x    = (const float*)d_in[0];
    const float* key  = (const float*)d_in[1];
    const float* val  = (const float*)d_in[2];
    const int*   mask = (const int*)d_in[3];
    const float* box  = (const float*)d_in[4];
    // d_in[5] road map: softmax-invariant, unused
    const float* Wq   = (const float*)d_in[6];
    const float* Wk   = (const float*)d_in[7];
    const float* Wv   = (const float*)d_in[8];
    const float* Wo   = (const float*)d_in[9];
    const float* bo   = (const float*)d_in[10];
    float*       out  = (float*)d_out;

    __nv_bfloat16 *xhi, *xlo, *khi, *klo, *vhi, *vlo;
    __nv_bfloat16 *wqhi, *wqlo, *wkhi, *wklo, *wvhi, *wvlo, *wohi, *wolo;
    __nv_bfloat16 *qhi, *qlo, *kphi, *kplo, *vthi, *vtlo, *phi, *plo, *aohi, *aolo;
    cudaGetSymbolAddress((void**)&xhi, g_xhi);   cudaGetSymbolAddress((void**)&xlo, g_xlo);
    cudaGetSymbolAddress((void**)&khi, g_khi);   cudaGetSymbolAddress((void**)&klo, g_klo);
    cudaGetSymbolAddress((void**)&vhi, g_vhi);   cudaGetSymbolAddress((void**)&vlo, g_vlo);
    cudaGetSymbolAddress((void**)&wqhi, g_wqhi); cudaGetSymbolAddress((void**)&wqlo, g_wqlo);
    cudaGetSymbolAddress((void**)&wkhi, g_wkhi); cudaGetSymbolAddress((void**)&wklo, g_wklo);
    cudaGetSymbolAddress((void**)&wvhi, g_wvhi); cudaGetSymbolAddress((void**)&wvlo, g_wvlo);
    cudaGetSymbolAddress((void**)&wohi, g_wohi); cudaGetSymbolAddress((void**)&wolo, g_wolo);
    cudaGetSymbolAddress((void**)&qhi, g_qhi);   cudaGetSymbolAddress((void**)&qlo, g_qlo);
    cudaGetSymbolAddress((void**)&kphi, g_kphi); cudaGetSymbolAddress((void**)&kplo, g_kplo);
    cudaGetSymbolAddress((void**)&vthi, g_vthi); cudaGetSymbolAddress((void**)&vtlo, g_vtlo);
    cudaGetSymbolAddress((void**)&phi, g_phi);   cudaGetSymbolAddress((void**)&plo, g_plo);
    cudaGetSymbolAddress((void**)&aohi, g_aohi); cudaGetSymbolAddress((void**)&aolo, g_aolo);

    constexpr int SMEM_G  = 3 * 2 * STAGE_B;                  // 61440
    constexpr int SMEM_QK = 2 * QK_QBUF + 2 * QK_KBUF;        // 59904
    constexpr int SMEM_PV = 2 * PV_PBUF + 2 * PV_VBUF;        // 67584
    cudaFuncSetAttribute(gemm_mma<1>, cudaFuncAttributeMaxDynamicSharedMemorySize, SMEM_G);
    cudaFuncSetAttribute(gemm_mma<2>, cudaFuncAttributeMaxDynamicSharedMemorySize, SMEM_G);
    cudaFuncSetAttribute(gemm_mma<3>, cudaFuncAttributeMaxDynamicSharedMemorySize, SMEM_G);
    cudaFuncSetAttribute(bgemm_qk, cudaFuncAttributeMaxDynamicSharedMemorySize, SMEM_QK);
    cudaFuncSetAttribute(bgemm_pv, cudaFuncAttributeMaxDynamicSharedMemorySize, SMEM_PV);

    auto split = [&](const float* src, __nv_bfloat16* h, __nv_bfloat16* l, int n) {
        int n4 = n / 4;
        split_kernel<<<(n4 + 255) / 256, 256>>>(src, h, l, n4);
    };
    split(x,   xhi, xlo, ROWS_Q * QD);
    split(key, khi, klo, ROWS_K * KD);
    split(val, vhi, vlo, ROWS_K * KD);
    split(Wq,  wqhi, wqlo, INNER * QD);
    split(Wk,  wkhi, wklo, INNER * KD);
    split(Wv,  wvhi, wvlo, INNER * KD);
    split(Wo,  wohi, wolo, QD * INNER);

    // projections -> bf16 hi/lo (V transposed per head)
    gemm_mma<2><<<dim3(INNER / 128, ROWS_Q / 128), 256, SMEM_G>>>(
        xhi, xlo, wqhi, wqlo, nullptr, nullptr, qhi, qlo, ROWS_Q, INNER, QD);
    gemm_mma<2><<<dim3(INNER / 128, ROWS_K / 128), 256, SMEM_G>>>(
        khi, klo, wkhi, wklo, nullptr, nullptr, kphi, kplo, ROWS_K, INNER, KD);
    gemm_mma<3><<<dim3(INNER / 128, ROWS_K / 128), 256, SMEM_G>>>(
        vhi, vlo, wvhi, wvlo, nullptr, nullptr, vthi, vtlo, ROWS_K, INNER, KD);

    // attention on tensor cores
    bgemm_qk<<<dim3(N_SZ / 128, B_SZ * HEADS), 256, SMEM_QK>>>(
        qhi, qlo, kphi, kplo, mask, box, phi, plo);
    bgemm_pv<<<dim3(N_SZ / 128, B_SZ * HEADS), 256, SMEM_PV>>>(
        phi, plo, vthi, vtlo, aohi, aolo);

    // output projection + bias
    gemm_mma<1><<<dim3((QD + 127) / 128, ROWS_Q / 128), 256, SMEM_G>>>(
        aohi, aolo, wohi, wolo, bo, out, nullptr, nullptr, ROWS_Q, QD, INNER);
}

// round 6
// speedup vs baseline: 4.7959x; 1.2247x over previous
#include <cuda_runtime.h>
#include <cuda_bf16.h>
#include <cstdint>

// ---------------------------------------------------------------------------
// CrossAttention, tensor-core mma.sync bf16 hi/lo (3-pass, fp32 accum).
// R6: 64x64 warp tiles in gemm (SMEM-read-bound fix) + fused flash-style
// attention (QK + mask/bias + softmax + PV in one kernel, P SMEM-resident).
// ---------------------------------------------------------------------------

#define B_SZ   32
#define N_SZ   1536
#define M_SZ   80
#define HEADS  8
#define CDIM   64
#define INNER  512
#define QD     320
#define KD     768
#define ROWS_Q (B_SZ * N_SZ)     // 49152
#define ROWS_K (B_SZ * M_SZ)     // 2560
#define SCALE  0.125f
#define LAMDA1 5.0f
#define BIGNEG (-3.402823466e38f)

// ---------------- scratch (device globals; allocation forbidden) -----------
__device__ __nv_bfloat16 g_xhi[ROWS_Q * QD],  g_xlo[ROWS_Q * QD];
__device__ __nv_bfloat16 g_khi[ROWS_K * KD],  g_klo[ROWS_K * KD];
__device__ __nv_bfloat16 g_vhi[ROWS_K * KD],  g_vlo[ROWS_K * KD];
__device__ __nv_bfloat16 g_wqhi[INNER * QD],  g_wqlo[INNER * QD];
__device__ __nv_bfloat16 g_wkhi[INNER * KD],  g_wklo[INNER * KD];
__device__ __nv_bfloat16 g_wvhi[INNER * KD],  g_wvlo[INNER * KD];
__device__ __nv_bfloat16 g_wohi[QD * INNER],  g_wolo[QD * INNER];
__device__ __nv_bfloat16 g_qhi [ROWS_Q * INNER], g_qlo [ROWS_Q * INNER];
__device__ __nv_bfloat16 g_kphi[ROWS_K * INNER], g_kplo[ROWS_K * INNER];
__device__ __nv_bfloat16 g_vthi[ROWS_K * INNER], g_vtlo[ROWS_K * INNER]; // [bh][c][m]
__device__ __nv_bfloat16 g_aohi[ROWS_Q * INNER], g_aolo[ROWS_Q * INNER];

// ---------------------------------------------------------------------------
// primitives
// ---------------------------------------------------------------------------
__device__ __forceinline__ uint32_t smem_u32(const void* p) {
    uint32_t a;
    asm("{ .reg .u64 t; cvta.to.shared.u64 t, %1; cvt.u32.u64 %0, t; }"
        : "=r"(a) : "l"(p));
    return a;
}
__device__ __forceinline__ void cp_async16(uint32_t dst, const void* src, uint32_t sz) {
    asm volatile("cp.async.cg.shared.global [%0], [%1], 16, %2;"
                 :: "r"(dst), "l"(src), "r"(sz));
}
__device__ __forceinline__ void cp_commit() { asm volatile("cp.async.commit_group;"); }
template <int N>
__device__ __forceinline__ void cp_wait() {
    asm volatile("cp.async.wait_group %0;" :: "n"(N));
}
__device__ __forceinline__ void ldmatrix_x4(uint32_t* r, uint32_t addr) {
    asm volatile("ldmatrix.sync.aligned.m8n8.x4.shared.b16 {%0,%1,%2,%3}, [%4];"
                 : "=r"(r[0]), "=r"(r[1]), "=r"(r[2]), "=r"(r[3]) : "r"(addr));
}
__device__ __forceinline__ void ldmatrix_x2(uint32_t* r, uint32_t addr) {
    asm volatile("ldmatrix.sync.aligned.m8n8.x2.shared.b16 {%0,%1}, [%2];"
                 : "=r"(r[0]), "=r"(r[1]) : "r"(addr));
}
__device__ __forceinline__ void mma16816(float* d, const uint32_t* a, const uint32_t* b) {
    asm volatile(
        "mma.sync.aligned.m16n8k16.row.col.f32.bf16.bf16.f32 "
        "{%0,%1,%2,%3}, {%4,%5,%6,%7}, {%8,%9}, {%0,%1,%2,%3};"
        : "+f"(d[0]), "+f"(d[1]), "+f"(d[2]), "+f"(d[3])
        : "r"(a[0]), "r"(a[1]), "r"(a[2]), "r"(a[3]), "r"(b[0]), "r"(b[1]));
}
__device__ __forceinline__ void split_store2(__nv_bfloat16* hi, __nv_bfloat16* lo,
                                             size_t idx, float v0, float v1) {
    __nv_bfloat16 h0 = __float2bfloat16(v0);
    __nv_bfloat16 h1 = __float2bfloat16(v1);
    *(__nv_bfloat162*)(hi + idx) = __halves2bfloat162(h0, h1);
    *(__nv_bfloat162*)(lo + idx) = __halves2bfloat162(
        __float2bfloat16(v0 - __bfloat162float(h0)),
        __float2bfloat16(v1 - __bfloat162float(h1)));
}
#define SWZ(off) ((off) ^ (((off) >> 3) & 0x70))

// ---------------------------------------------------------------------------
// split: fp32 -> (hi, lo) bf16
// ---------------------------------------------------------------------------
__global__ void split_kernel(const float* __restrict__ in,
                             __nv_bfloat16* __restrict__ hi,
                             __nv_bfloat16* __restrict__ lo, int n4)
{
    int i = blockIdx.x * blockDim.x + threadIdx.x;
    if (i >= n4) return;
    float4 v = ((const float4*)in)[i];
    split_store2(hi, lo, (size_t)i * 4,     v.x, v.y);
    split_store2(hi, lo, (size_t)i * 4 + 2, v.z, v.w);
}

// ---------------------------------------------------------------------------
// GEMM: C[r,c] = sum_k A[r,k]*B[c,k], hi/lo 3-pass (segments).
// 128 threads, 4 warps in 2x2, warp tile 64x64. BM=BN=128, BK=32, 3 stages.
// MODE 1: fp32 + bias. MODE 2: bf16 hi/lo out (scaled). MODE 3: per-head-
// transposed bf16 hi/lo (V: vt[(b*8+h)*64+c][m]).
// ---------------------------------------------------------------------------
#define STAGE_B (128 * 40 * 2)   // 10240 bytes per operand per stage
#define KCHUNK  32

template <int MODE>
__global__ void __launch_bounds__(128, 2)
gemm_mma(const __nv_bfloat16* __restrict__ Ahi, const __nv_bfloat16* __restrict__ Alo,
         const __nv_bfloat16* __restrict__ Bhi, const __nv_bfloat16* __restrict__ Blo,
         const float* __restrict__ bias, float* __restrict__ Cf,
         __nv_bfloat16* __restrict__ Chi, __nv_bfloat16* __restrict__ Clo,
         int rows, int cols, int K, float ascale)
{
    extern __shared__ char smem[];
    const uint32_t sbase = smem_u32(smem);

    const int tid  = threadIdx.x;
    const int wid  = tid >> 5;
    const int lane = tid & 31;
    const int wm   = wid >> 1;           // 0..1
    const int wn   = wid & 1;            // 0..1

    const int rbase = blockIdx.y * 128;
    const int cbase = blockIdx.x * 128;
    const int KC    = K / KCHUNK;
    const int KT    = 3 * KC;

    auto load_stage = [&](int it, int stage) {
        const int seg = it / KC;
        const __nv_bfloat16* Ap = (seg == 2) ? Alo : Ahi;
        const __nv_bfloat16* Bp = (seg == 1) ? Blo : Bhi;
        const int kb = (it - seg * KC) * KCHUNK;
        const uint32_t abase = sbase + stage * 2 * STAGE_B;
        const uint32_t bbase = abase + STAGE_B;
#pragma unroll
        for (int t = 0; t < 4; t++) {           // A: 512 chunks
            const int task = t * 128 + tid;
            const int row  = task >> 2;
            const int ch   = task & 3;
            cp_async16(abase + row * 80 + ch * 16,
                       Ap + (size_t)(rbase + row) * K + kb + ch * 8, 16);
        }
#pragma unroll
        for (int t = 0; t < 4; t++) {           // B: 512 chunks
            const int task = t * 128 + tid;
            const int row  = task >> 2;
            const int ch   = task & 3;
            const int col   = cbase + row;
            const int valid = (col < cols);
            cp_async16(bbase + row * 80 + ch * 16,
                       Bp + (size_t)(valid ? col : 0) * K + kb + ch * 8,
                       valid ? 16u : 0u);
        }
        cp_commit();
    };

    float acc[4][8][4];
#pragma unroll
    for (int i = 0; i < 4; i++)
#pragma unroll
        for (int j = 0; j < 8; j++)
#pragma unroll
            for (int e = 0; e < 4; e++) acc[i][j][e] = 0.0f;

    load_stage(0, 0);
    load_stage(1, 1);

    const int g  = lane >> 3;
    const int r8 = lane & 7;
    const int a_row_off = (g & 1) * 8 + r8;       // A frag
    const int a_k_off   = (g >> 1) * 16;
    const int bx_row_off = (g >> 1) * 8 + r8;     // B x4 trick
    const int bx_k_off   = (g & 1) * 16;

    for (int it = 0; it < KT; it++) {
        cp_wait<1>();
        __syncthreads();
        if (it + 2 < KT) load_stage(it + 2, (it + 2) % 3);
        else cp_commit();

        const int stage = it % 3;
        const uint32_t sA = sbase + stage * 2 * STAGE_B;
        const uint32_t sB = sA + STAGE_B;

#pragma unroll
        for (int s = 0; s < 2; s++) {
            uint32_t afrag[4][4];
            uint32_t bfrag[8][2];
#pragma unroll
            for (int i = 0; i < 4; i++)
                ldmatrix_x4(afrag[i],
                    sA + (wm * 64 + i * 16 + a_row_off) * 80 + s * 32 + a_k_off);
#pragma unroll
            for (int jj = 0; jj < 4; jj++) {
                uint32_t r[4];
                ldmatrix_x4(r,
                    sB + (wn * 64 + jj * 16 + bx_row_off) * 80 + s * 32 + bx_k_off);
                bfrag[jj * 2][0]     = r[0]; bfrag[jj * 2][1]     = r[1];
                bfrag[jj * 2 + 1][0] = r[2]; bfrag[jj * 2 + 1][1] = r[3];
            }
#pragma unroll
            for (int i = 0; i < 4; i++)
#pragma unroll
                for (int j = 0; j < 8; j++)
                    mma16816(acc[i][j], afrag[i], bfrag[j]);
        }
        __syncthreads();
    }

    const int qrow = lane >> 2;
    const int qcol = (lane & 3) * 2;
#pragma unroll
    for (int i = 0; i < 4; i++) {
        const int row0 = rbase + wm * 64 + i * 16 + qrow;
#pragma unroll
        for (int j = 0; j < 8; j++) {
            const int col0 = cbase + wn * 64 + j * 8 + qcol;
            if (col0 >= cols) continue;
            if (MODE == 1) {
                const float b0 = bias[col0], b1 = bias[col0 + 1];
                *(float2*)(Cf + (size_t)row0 * cols + col0) =
                    make_float2(acc[i][j][0] + b0, acc[i][j][1] + b1);
                *(float2*)(Cf + (size_t)(row0 + 8) * cols + col0) =
                    make_float2(acc[i][j][2] + b0, acc[i][j][3] + b1);
            } else if (MODE == 2) {
                split_store2(Chi, Clo, (size_t)row0 * cols + col0,
                             acc[i][j][0] * ascale, acc[i][j][1] * ascale);
                split_store2(Chi, Clo, (size_t)(row0 + 8) * cols + col0,
                             acc[i][j][2] * ascale, acc[i][j][3] * ascale);
            } else { // MODE 3
#pragma unroll
                for (int rr = 0; rr < 2; rr++) {
                    const int r = row0 + rr * 8;
                    const int bb = r / M_SZ;
                    const int m  = r - bb * M_SZ;
#pragma unroll
                    for (int cc = 0; cc < 2; cc++) {
                        const int col = col0 + cc;
                        const int idx = (bb * HEADS + (col >> 6)) * CDIM + (col & 63);
                        const float v = acc[i][j][rr * 2 + cc];
                        __nv_bfloat16 h = __float2bfloat16(v);
                        Chi[(size_t)idx * M_SZ + m] = h;
                        Clo[(size_t)idx * M_SZ + m] =
                            __float2bfloat16(v - __bfloat162float(h));
                    }
                }
            }
        }
    }
}

// ---------------------------------------------------------------------------
// Fused attention: per (b,h,ntile=128): S = QK^T (q pre-scaled), mask + box
// bias, softmax, P (bf16 hi/lo, SMEM-resident), O = P*Vt, ao hi/lo out.
// 128 threads, 4 warps 2x2. SMEM regions (bytes):
//   [0, 32768)      Q hi/lo (128x128B swizzled)   -> reused for Vt hi/lo
//   [32768, 53248)  K hi/lo (80x128B swizzled)    -> reused for P (with box)
//   [53248, 94208)  box fp32 (128 x 320B)         -> tail reused by P lo
//   [94208, 96576)  rmax/rsum (512 f32) + mask (80 i32)
// P: hi at 32768, lo at 55296 (pitch 176B, 22528 each; box consumed first).
// ---------------------------------------------------------------------------
#define AT_QBUF  16384
#define AT_KBASE 32768
#define AT_KBUF  10240
#define AT_BOX   53248
#define AT_RED   94208
#define AT_P     32768
#define AT_PBUF  22528
#define AT_VBUF  11264
#define AT_SMEM  96576

__global__ void __launch_bounds__(128, 2)
attn_fused(const __nv_bfloat16* __restrict__ qhi, const __nv_bfloat16* __restrict__ qlo,
           const __nv_bfloat16* __restrict__ khi, const __nv_bfloat16* __restrict__ klo,
           const __nv_bfloat16* __restrict__ vthi, const __nv_bfloat16* __restrict__ vtlo,
           const int* __restrict__ mask, const float* __restrict__ box,
           __nv_bfloat16* __restrict__ aohi, __nv_bfloat16* __restrict__ aolo)
{
    extern __shared__ char smem[];
    const uint32_t sbase = smem_u32(smem);
    const int tid  = threadIdx.x;
    const int wid  = tid >> 5;
    const int lane = tid & 31;
    const int wr   = wid >> 1;           // 0..1 : 64-row halves
    const int wc   = wid & 1;            // 0..1 : col halves
    const int bh   = blockIdx.y;
    const int b    = bh >> 3, h = bh & 7;
    const int nbase = blockIdx.x * 128;

    int* smask = (int*)(smem + AT_RED + 2048);
    if (tid < M_SZ) smask[tid] = mask[b * M_SZ + tid];

    // Q: 2 bufs x 128 rows x 8 chunks
    const __nv_bfloat16* qsrc[2] = {qhi, qlo};
#pragma unroll
    for (int u = 0; u < 16; u++) {
        const int task = u * 128 + tid;
        const int buf  = task >> 10;
        const int rem  = task & 1023;
        const int row  = rem >> 3, ch = rem & 7;
        cp_async16(sbase + buf * AT_QBUF + SWZ(row * 128 + ch * 16),
                   qsrc[buf] + (size_t)(b * N_SZ + nbase + row) * INNER + h * CDIM + ch * 8, 16);
    }
    // K: 2 bufs x 80 rows x 8 chunks
    const __nv_bfloat16* ksrc[2] = {khi, klo};
#pragma unroll
    for (int u = 0; u < 10; u++) {
        const int task = u * 128 + tid;
        const int buf  = task >= 640;
        const int rem  = task - buf * 640;
        const int row  = rem >> 3, ch = rem & 7;
        cp_async16(sbase + AT_KBASE + buf * AT_KBUF + SWZ(row * 128 + ch * 16),
                   ksrc[buf] + (size_t)(b * M_SZ + row) * INNER + h * CDIM + ch * 8, 16);
    }
    // box: 128 rows x 20 chunks (80 fp32)
#pragma unroll
    for (int u = 0; u < 20; u++) {
        const int task = u * 128 + tid;
        const int row  = task / 20, ch = task - row * 20;
        cp_async16(sbase + AT_BOX + row * 320 + ch * 16,
                   box + (size_t)(b * N_SZ + nbase + row) * M_SZ + ch * 4, 16);
    }
    cp_commit();
    cp_wait<0>();
    __syncthreads();

    const int g  = lane >> 3;
    const int r8 = lane & 7;
    const int a_row_off = (g & 1) * 8 + r8;
    const int a_k_off   = (g >> 1) * 16;

    // ---- QK (3 passes, K=64) ----
    float acc[4][5][4];
#pragma unroll
    for (int i = 0; i < 4; i++)
#pragma unroll
        for (int j = 0; j < 5; j++)
#pragma unroll
            for (int e = 0; e < 4; e++) acc[i][j][e] = 0.0f;

#pragma unroll
    for (int p = 0; p < 3; p++) {
        const uint32_t qb = sbase + ((p == 2) ? AT_QBUF : 0);
        const uint32_t kb = sbase + AT_KBASE + ((p == 1) ? AT_KBUF : 0);
#pragma unroll
        for (int ks = 0; ks < 4; ks++) {
            uint32_t af[4][4], bf[5][2];
#pragma unroll
            for (int i = 0; i < 4; i++)
                ldmatrix_x4(af[i], qb + SWZ((wr * 64 + i * 16 + a_row_off) * 128
                                            + ks * 32 + a_k_off));
#pragma unroll
            for (int j = 0; j < 5; j++)
                ldmatrix_x2(bf[j], kb + SWZ((wc * 40 + j * 8 + r8) * 128
                                            + ks * 32 + (g & 1) * 16));
#pragma unroll
            for (int i = 0; i < 4; i++)
#pragma unroll
                for (int j = 0; j < 5; j++)
                    mma16816(acc[i][j], af[i], bf[j]);
        }
    }
    __syncthreads();    // all warps done reading Q/K smem

    // ---- Vt loads into Q region (overlaps softmax) ----
    const __nv_bfloat16* vsrc[2] = {vthi, vtlo};
#pragma unroll
    for (int u = 0; u < 10; u++) {
        const int task = u * 128 + tid;
        const int buf  = task >= 640;
        const int rem  = task - buf * 640;
        const int row  = rem / 10, ch = rem - row * 10;
        cp_async16(sbase + buf * AT_VBUF + row * 176 + ch * 16,
                   vsrc[buf] + ((size_t)bh * CDIM + row) * M_SZ + ch * 8, 16);
    }
    cp_commit();

    // ---- mask + box bias into registers (consumes box smem) ----
    const float* boxS = (const float*)(smem + AT_BOX);
    const int qrow = lane >> 2;
    const int qcol = (lane & 3) * 2;
#pragma unroll
    for (int i = 0; i < 4; i++)
#pragma unroll
        for (int j = 0; j < 5; j++)
#pragma unroll
            for (int e = 0; e < 4; e++) {
                const int r = wr * 64 + i * 16 + qrow + (e >> 1) * 8;
                const int c = wc * 40 + j * 8 + qcol + (e & 1);
                acc[i][j][e] = smask[c]
                    ? acc[i][j][e] + LAMDA1 * boxS[r * 80 + c] : BIGNEG;
            }

    // ---- softmax: row max ----
    float* rmax = (float*)(smem + AT_RED);
    float* rsum = rmax + 256;
    float rm[4][2];
#pragma unroll
    for (int i = 0; i < 4; i++)
#pragma unroll
        for (int hf = 0; hf < 2; hf++) {
            float m = BIGNEG;
#pragma unroll
            for (int j = 0; j < 5; j++)
                m = fmaxf(m, fmaxf(acc[i][j][hf * 2], acc[i][j][hf * 2 + 1]));
            m = fmaxf(m, __shfl_xor_sync(0xffffffffu, m, 1));
            m = fmaxf(m, __shfl_xor_sync(0xffffffffu, m, 2));
            rm[i][hf] = m;
        }
    if ((lane & 3) == 0)
#pragma unroll
        for (int i = 0; i < 4; i++)
#pragma unroll
            for (int hf = 0; hf < 2; hf++)
                rmax[wc * 128 + wr * 64 + i * 16 + qrow + hf * 8] = rm[i][hf];
    __syncthreads();

    // ---- exp + row sum ----
    float rs[4][2];
#pragma unroll
    for (int i = 0; i < 4; i++)
#pragma unroll
        for (int hf = 0; hf < 2; hf++) {
            const int r = wr * 64 + i * 16 + qrow + hf * 8;
            const float m = fmaxf(rmax[r], rmax[128 + r]);
            float s = 0.0f;
#pragma unroll
            for (int j = 0; j < 5; j++) {
                acc[i][j][hf * 2]     = __expf(acc[i][j][hf * 2]     - m);
                acc[i][j][hf * 2 + 1] = __expf(acc[i][j][hf * 2 + 1] - m);
                s += acc[i][j][hf * 2] + acc[i][j][hf * 2 + 1];
            }
            s += __shfl_xor_sync(0xffffffffu, s, 1);
            s += __shfl_xor_sync(0xffffffffu, s, 2);
            rs[i][hf] = s;
        }
    if ((lane & 3) == 0)
#pragma unroll
        for (int i = 0; i < 4; i++)
#pragma unroll
            for (int hf = 0; hf < 2; hf++)
                rsum[wc * 128 + wr * 64 + i * 16 + qrow + hf * 8] = rs[i][hf];
    __syncthreads();

    // ---- normalize, store P (bf16 hi/lo) into K/box region ----
#pragma unroll
    for (int i = 0; i < 4; i++)
#pragma unroll
        for (int hf = 0; hf < 2; hf++) {
            const int r = wr * 64 + i * 16 + qrow + hf * 8;
            const float inv = 1.0f / (rsum[r] + rsum[128 + r]);
#pragma unroll
            for (int j = 0; j < 5; j++) {
                const int c0 = wc * 40 + j * 8 + qcol;
                const float p0 = acc[i][j][hf * 2] * inv;
                const float p1 = acc[i][j][hf * 2 + 1] * inv;
                __nv_bfloat16 h0 = __float2bfloat16(p0);
                __nv_bfloat16 h1 = __float2bfloat16(p1);
                *(__nv_bfloat162*)(smem + AT_P + r * 176 + c0 * 2) =
                    __halves2bfloat162(h0, h1);
                *(__nv_bfloat162*)(smem + AT_P + AT_PBUF + r * 176 + c0 * 2) =
                    __halves2bfloat162(
                        __float2bfloat16(p0 - __bfloat162float(h0)),
                        __float2bfloat16(p1 - __bfloat162float(h1)));
            }
        }
    cp_wait<0>();
    __syncthreads();

    // ---- PV (3 passes, K=80) ----
    float acc2[4][4][4];
#pragma unroll
    for (int i = 0; i < 4; i++)
#pragma unroll
        for (int j = 0; j < 4; j++)
#pragma unroll
            for (int e = 0; e < 4; e++) acc2[i][j][e] = 0.0f;

#pragma unroll
    for (int p = 0; p < 3; p++) {
        const uint32_t pb = sbase + AT_P + ((p == 2) ? AT_PBUF : 0);
        const uint32_t vb = sbase + ((p == 1) ? AT_VBUF : 0);
#pragma unroll
        for (int ks = 0; ks < 5; ks++) {
            uint32_t af[4][4], bf[4][2];
#pragma unroll
            for (int i = 0; i < 4; i++)
                ldmatrix_x4(af[i], pb + (wr * 64 + i * 16 + a_row_off) * 176
                                      + ks * 32 + a_k_off);
#pragma unroll
            for (int j = 0; j < 4; j++)
                ldmatrix_x2(bf[j], vb + (wc * 32 + j * 8 + r8) * 176
                                      + ks * 32 + (g & 1) * 16);
#pragma unroll
            for (int i = 0; i < 4; i++)
#pragma unroll
                for (int j = 0; j < 4; j++)
                    mma16816(acc2[i][j], af[i], bf[j]);
        }
    }

    // ---- ao hi/lo out ----
#pragma unroll
    for (int i = 0; i < 4; i++) {
        const int n0 = nbase + wr * 64 + i * 16 + qrow;
#pragma unroll
        for (int j = 0; j < 4; j++) {
            const int c0 = wc * 32 + j * 8 + qcol;
            const size_t i0 = (size_t)(b * N_SZ + n0) * INNER + h * CDIM + c0;
            split_store2(aohi, aolo, i0,                       acc2[i][j][0], acc2[i][j][1]);
            split_store2(aohi, aolo, i0 + (size_t)8 * INNER,   acc2[i][j][2], acc2[i][j][3]);
        }
    }
}

// ---------------------------------------------------------------------------
// Launch
// ---------------------------------------------------------------------------
extern "C" void kernel_launch(void* const* d_in, const int* in_sizes, int n_in,
                              void* d_out, int out_size)
{
    const float* x    = (const float*)d_in[0];
    const float* key  = (const float*)d_in[1];
    const float* val  = (const float*)d_in[2];
    const int*   mask = (const int*)d_in[3];
    const float* box  = (const float*)d_in[4];
    // d_in[5] road map: softmax-invariant, unused
    const float* Wq   = (const float*)d_in[6];
    const float* Wk   = (const float*)d_in[7];
    const float* Wv   = (const float*)d_in[8];
    const float* Wo   = (const float*)d_in[9];
    const float* bo   = (const float*)d_in[10];
    float*       out  = (float*)d_out;

    __nv_bfloat16 *xhi, *xlo, *khi, *klo, *vhi, *vlo;
    __nv_bfloat16 *wqhi, *wqlo, *wkhi, *wklo, *wvhi, *wvlo, *wohi, *wolo;
    __nv_bfloat16 *qhi, *qlo, *kphi, *kplo, *vthi, *vtlo, *aohi, *aolo;
    cudaGetSymbolAddress((void**)&xhi, g_xhi);   cudaGetSymbolAddress((void**)&xlo, g_xlo);
    cudaGetSymbolAddress((void**)&khi, g_khi);   cudaGetSymbolAddress((void**)&klo, g_klo);
    cudaGetSymbolAddress((void**)&vhi, g_vhi);   cudaGetSymbolAddress((void**)&vlo, g_vlo);
    cudaGetSymbolAddress((void**)&wqhi, g_wqhi); cudaGetSymbolAddress((void**)&wqlo, g_wqlo);
    cudaGetSymbolAddress((void**)&wkhi, g_wkhi); cudaGetSymbolAddress((void**)&wklo, g_wklo);
    cudaGetSymbolAddress((void**)&wvhi, g_wvhi); cudaGetSymbolAddress((void**)&wvlo, g_wvlo);
    cudaGetSymbolAddress((void**)&wohi, g_wohi); cudaGetSymbolAddress((void**)&wolo, g_wolo);
    cudaGetSymbolAddress((void**)&qhi, g_qhi);   cudaGetSymbolAddress((void**)&qlo, g_qlo);
    cudaGetSymbolAddress((void**)&kphi, g_kphi); cudaGetSymbolAddress((void**)&kplo, g_kplo);
    cudaGetSymbolAddress((void**)&vthi, g_vthi); cudaGetSymbolAddress((void**)&vtlo, g_vtlo);
    cudaGetSymbolAddress((void**)&aohi, g_aohi); cudaGetSymbolAddress((void**)&aolo, g_aolo);

    constexpr int SMEM_G = 3 * 2 * STAGE_B;     // 61440
    cudaFuncSetAttribute(gemm_mma<1>, cudaFuncAttributeMaxDynamicSharedMemorySize, SMEM_G);
    cudaFuncSetAttribute(gemm_mma<2>, cudaFuncAttributeMaxDynamicSharedMemorySize, SMEM_G);
    cudaFuncSetAttribute(gemm_mma<3>, cudaFuncAttributeMaxDynamicSharedMemorySize, SMEM_G);
    cudaFuncSetAttribute(attn_fused, cudaFuncAttributeMaxDynamicSharedMemorySize, AT_SMEM);

    auto split = [&](const float* src, __nv_bfloat16* h, __nv_bfloat16* l, int n) {
        int n4 = n / 4;
        split_kernel<<<(n4 + 255) / 256, 256>>>(src, h, l, n4);
    };
    split(x,   xhi, xlo, ROWS_Q * QD);
    split(key, khi, klo, ROWS_K * KD);
    split(val, vhi, vlo, ROWS_K * KD);
    split(Wq,  wqhi, wqlo, INNER * QD);
    split(Wk,  wkhi, wklo, INNER * KD);
    split(Wv,  wvhi, wvlo, INNER * KD);
    split(Wo,  wohi, wolo, QD * INNER);

    // projections (Q pre-scaled by SCALE; V per-head-transposed)
    gemm_mma<2><<<dim3(INNER / 128, ROWS_Q / 128), 128, SMEM_G>>>(
        xhi, xlo, wqhi, wqlo, nullptr, nullptr, qhi, qlo, ROWS_Q, INNER, QD, SCALE);
    gemm_mma<2><<<dim3(INNER / 128, ROWS_K / 128), 128, SMEM_G>>>(
        khi, klo, wkhi, wklo, nullptr, nullptr, kphi, kplo, ROWS_K, INNER, KD, 1.0f);
    gemm_mma<3><<<dim3(INNER / 128, ROWS_K / 128), 128, SMEM_G>>>(
        vhi, vlo, wvhi, wvlo, nullptr, nullptr, vthi, vtlo, ROWS_K, INNER, KD, 1.0f);

    // fused attention
    attn_fused<<<dim3(N_SZ / 128, B_SZ * HEADS), 128, AT_SMEM>>>(
        qhi, qlo, kphi, kplo, vthi, vtlo, mask, box, aohi, aolo);

    // output projection + bias
    gemm_mma<1><<<dim3((QD + 127) / 128, ROWS_Q / 128), 128, SMEM_G>>>(
        aohi, aolo, wohi, wolo, bo, out, nullptr, nullptr, ROWS_Q, QD, INNER, 1.0f);
}

// round 7
// speedup vs baseline: 5.5805x; 1.1636x over previous
#include <cuda_runtime.h>
#include <cuda_bf16.h>
#include <cstdint>

// ---------------------------------------------------------------------------
// CrossAttention, tensor-core mma.sync bf16 hi/lo (3-pass, fp32 accum).
// R7: launch consolidation — 1 split kernel (all 7 tensors), 1 projection
// kernel (Q,K,V via blockIdx.z), fused attention, O-proj. 4 launches total.
// ---------------------------------------------------------------------------

#define B_SZ   32
#define N_SZ   1536
#define M_SZ   80
#define HEADS  8
#define CDIM   64
#define INNER  512
#define QD     320
#define KD     768
#define ROWS_Q (B_SZ * N_SZ)     // 49152
#define ROWS_K (B_SZ * M_SZ)     // 2560
#define SCALE  0.125f
#define LAMDA1 5.0f
#define BIGNEG (-3.402823466e38f)

// ---------------- scratch (device globals; allocation forbidden) -----------
__device__ __nv_bfloat16 g_xhi[ROWS_Q * QD],  g_xlo[ROWS_Q * QD];
__device__ __nv_bfloat16 g_khi[ROWS_K * KD],  g_klo[ROWS_K * KD];
__device__ __nv_bfloat16 g_vhi[ROWS_K * KD],  g_vlo[ROWS_K * KD];
__device__ __nv_bfloat16 g_wqhi[INNER * QD],  g_wqlo[INNER * QD];
__device__ __nv_bfloat16 g_wkhi[INNER * KD],  g_wklo[INNER * KD];
__device__ __nv_bfloat16 g_wvhi[INNER * KD],  g_wvlo[INNER * KD];
__device__ __nv_bfloat16 g_wohi[QD * INNER],  g_wolo[QD * INNER];
__device__ __nv_bfloat16 g_qhi [ROWS_Q * INNER], g_qlo [ROWS_Q * INNER];
__device__ __nv_bfloat16 g_kphi[ROWS_K * INNER], g_kplo[ROWS_K * INNER];
__device__ __nv_bfloat16 g_vthi[ROWS_K * INNER], g_vtlo[ROWS_K * INNER]; // [bh][c][m]
__device__ __nv_bfloat16 g_aohi[ROWS_Q * INNER], g_aolo[ROWS_Q * INNER];

// ---------------------------------------------------------------------------
// primitives
// ---------------------------------------------------------------------------
__device__ __forceinline__ uint32_t smem_u32(const void* p) {
    uint32_t a;
    asm("{ .reg .u64 t; cvta.to.shared.u64 t, %1; cvt.u32.u64 %0, t; }"
        : "=r"(a) : "l"(p));
    return a;
}
__device__ __forceinline__ void cp_async16(uint32_t dst, const void* src, uint32_t sz) {
    asm volatile("cp.async.cg.shared.global [%0], [%1], 16, %2;"
                 :: "r"(dst), "l"(src), "r"(sz));
}
__device__ __forceinline__ void cp_commit() { asm volatile("cp.async.commit_group;"); }
template <int N>
__device__ __forceinline__ void cp_wait() {
    asm volatile("cp.async.wait_group %0;" :: "n"(N));
}
__device__ __forceinline__ void ldmatrix_x4(uint32_t* r, uint32_t addr) {
    asm volatile("ldmatrix.sync.aligned.m8n8.x4.shared.b16 {%0,%1,%2,%3}, [%4];"
                 : "=r"(r[0]), "=r"(r[1]), "=r"(r[2]), "=r"(r[3]) : "r"(addr));
}
__device__ __forceinline__ void ldmatrix_x2(uint32_t* r, uint32_t addr) {
    asm volatile("ldmatrix.sync.aligned.m8n8.x2.shared.b16 {%0,%1}, [%2];"
                 : "=r"(r[0]), "=r"(r[1]) : "r"(addr));
}
__device__ __forceinline__ void mma16816(float* d, const uint32_t* a, const uint32_t* b) {
    asm volatile(
        "mma.sync.aligned.m16n8k16.row.col.f32.bf16.bf16.f32 "
        "{%0,%1,%2,%3}, {%4,%5,%6,%7}, {%8,%9}, {%0,%1,%2,%3};"
        : "+f"(d[0]), "+f"(d[1]), "+f"(d[2]), "+f"(d[3])
        : "r"(a[0]), "r"(a[1]), "r"(a[2]), "r"(a[3]), "r"(b[0]), "r"(b[1]));
}
__device__ __forceinline__ void split_store2(__nv_bfloat16* hi, __nv_bfloat16* lo,
                                             size_t idx, float v0, float v1) {
    __nv_bfloat16 h0 = __float2bfloat16(v0);
    __nv_bfloat16 h1 = __float2bfloat16(v1);
    *(__nv_bfloat162*)(hi + idx) = __halves2bfloat162(h0, h1);
    *(__nv_bfloat162*)(lo + idx) = __halves2bfloat162(
        __float2bfloat16(v0 - __bfloat162float(h0)),
        __float2bfloat16(v1 - __bfloat162float(h1)));
}
#define SWZ(off) ((off) ^ (((off) >> 3) & 0x70))

// ---------------------------------------------------------------------------
// mega-split: all 7 fp32 tensors -> bf16 hi/lo in one launch.
// Segment boundaries in float4 units (compile-time).
// ---------------------------------------------------------------------------
#define N4_X   (ROWS_Q * QD / 4)        // 3,932,160
#define N4_KEY (ROWS_K * KD / 4)        //   491,520
#define N4_VAL (ROWS_K * KD / 4)
#define N4_WQ  (INNER * QD / 4)         //    40,960
#define N4_WK  (INNER * KD / 4)         //    98,304
#define N4_WV  (INNER * KD / 4)
#define N4_WO  (QD * INNER / 4)         //    40,960
#define S1 (N4_X)
#define S2 (S1 + N4_KEY)
#define S3 (S2 + N4_VAL)
#define S4 (S3 + N4_WQ)
#define S5 (S4 + N4_WK)
#define S6 (S5 + N4_WV)
#define S7 (S6 + N4_WO)                 // 5,193,728 total float4s

__global__ void __launch_bounds__(256)
split_all(const float* __restrict__ x,   const float* __restrict__ key,
          const float* __restrict__ val, const float* __restrict__ wq,
          const float* __restrict__ wk,  const float* __restrict__ wv,
          const float* __restrict__ wo,
          __nv_bfloat16* __restrict__ xhi, __nv_bfloat16* __restrict__ xlo,
          __nv_bfloat16* __restrict__ khi, __nv_bfloat16* __restrict__ klo,
          __nv_bfloat16* __restrict__ vhi, __nv_bfloat16* __restrict__ vlo,
          __nv_bfloat16* __restrict__ wqhi, __nv_bfloat16* __restrict__ wqlo,
          __nv_bfloat16* __restrict__ wkhi, __nv_bfloat16* __restrict__ wklo,
          __nv_bfloat16* __restrict__ wvhi, __nv_bfloat16* __restrict__ wvlo,
          __nv_bfloat16* __restrict__ wohi, __nv_bfloat16* __restrict__ wolo)
{
    const int i = blockIdx.x * blockDim.x + threadIdx.x;
    if (i >= S7) return;

    const float* src; __nv_bfloat16 *hi, *lo; int off;
    if      (i < S1) { src = x;   hi = xhi;  lo = xlo;  off = i;      }
    else if (i < S2) { src = key; hi = khi;  lo = klo;  off = i - S1; }
    else if (i < S3) { src = val; hi = vhi;  lo = vlo;  off = i - S2; }
    else if (i < S4) { src = wq;  hi = wqhi; lo = wqlo; off = i - S3; }
    else if (i < S5) { src = wk;  hi = wkhi; lo = wklo; off = i - S4; }
    else if (i < S6) { src = wv;  hi = wvhi; lo = wvlo; off = i - S5; }
    else             { src = wo;  hi = wohi; lo = wolo; off = i - S6; }

    float4 v = ((const float4*)src)[off];
    split_store2(hi, lo, (size_t)off * 4,     v.x, v.y);
    split_store2(hi, lo, (size_t)off * 4 + 2, v.z, v.w);
}

// ---------------------------------------------------------------------------
// shared GEMM mainloop body (BM=BN=128, BK=32, 4 warps 2x2, 64x64 warp tiles,
// 3-stage cp.async, hi/lo 3-pass). Used by gemm_proj and gemm_out.
// ---------------------------------------------------------------------------
#define STAGE_B (128 * 40 * 2)   // 10240 bytes per operand per stage
#define KCHUNK  32

struct GemmCore {
    uint32_t sbase;
    int tid, wid, lane, wm, wn;
    int g, r8, a_row_off, a_k_off, bx_row_off, bx_k_off;

    __device__ __forceinline__ void init(uint32_t sb, int t) {
        sbase = sb; tid = t;
        wid = t >> 5; lane = t & 31;
        wm = wid >> 1; wn = wid & 1;
        g = lane >> 3; r8 = lane & 7;
        a_row_off = (g & 1) * 8 + r8;
        a_k_off   = (g >> 1) * 16;
        bx_row_off = (g >> 1) * 8 + r8;
        bx_k_off   = (g & 1) * 16;
    }

    template <bool GUARD>
    __device__ __forceinline__ void load_stage(
        const __nv_bfloat16* Ahi, const __nv_bfloat16* Alo,
        const __nv_bfloat16* Bhi, const __nv_bfloat16* Blo,
        int rbase, int cbase, int cols, int K, int KC, int it, int stage)
    {
        const int seg = it / KC;
        const __nv_bfloat16* Ap = (seg == 2) ? Alo : Ahi;
        const __nv_bfloat16* Bp = (seg == 1) ? Blo : Bhi;
        const int kb = (it - seg * KC) * KCHUNK;
        const uint32_t abase = sbase + stage * 2 * STAGE_B;
        const uint32_t bbase = abase + STAGE_B;
#pragma unroll
        for (int t = 0; t < 4; t++) {
            const int task = t * 128 + tid;
            const int row  = task >> 2;
            const int ch   = task & 3;
            cp_async16(abase + row * 80 + ch * 16,
                       Ap + (size_t)(rbase + row) * K + kb + ch * 8, 16);
        }
#pragma unroll
        for (int t = 0; t < 4; t++) {
            const int task = t * 128 + tid;
            const int row  = task >> 2;
            const int ch   = task & 3;
            if (GUARD) {
                const int col   = cbase + row;
                const int valid = (col < cols);
                cp_async16(bbase + row * 80 + ch * 16,
                           Bp + (size_t)(valid ? col : 0) * K + kb + ch * 8,
                           valid ? 16u : 0u);
            } else {
                cp_async16(bbase + row * 80 + ch * 16,
                           Bp + (size_t)(cbase + row) * K + kb + ch * 8, 16);
            }
        }
        cp_commit();
    }

    template <bool GUARD>
    __device__ __forceinline__ void run(
        float acc[4][8][4],
        const __nv_bfloat16* Ahi, const __nv_bfloat16* Alo,
        const __nv_bfloat16* Bhi, const __nv_bfloat16* Blo,
        int rbase, int cbase, int cols, int K)
    {
        const int KC = K / KCHUNK;
        const int KT = 3 * KC;
        load_stage<GUARD>(Ahi, Alo, Bhi, Blo, rbase, cbase, cols, K, KC, 0, 0);
        load_stage<GUARD>(Ahi, Alo, Bhi, Blo, rbase, cbase, cols, K, KC, 1, 1);

        for (int it = 0; it < KT; it++) {
            cp_wait<1>();
            __syncthreads();
            if (it + 2 < KT)
                load_stage<GUARD>(Ahi, Alo, Bhi, Blo, rbase, cbase, cols, K, KC,
                                  it + 2, (it + 2) % 3);
            else cp_commit();

            const int stage = it % 3;
            const uint32_t sA = sbase + stage * 2 * STAGE_B;
            const uint32_t sB = sA + STAGE_B;
#pragma unroll
            for (int s = 0; s < 2; s++) {
                uint32_t afrag[4][4];
                uint32_t bfrag[8][2];
#pragma unroll
                for (int i = 0; i < 4; i++)
                    ldmatrix_x4(afrag[i],
                        sA + (wm * 64 + i * 16 + a_row_off) * 80 + s * 32 + a_k_off);
#pragma unroll
                for (int jj = 0; jj < 4; jj++) {
                    uint32_t r[4];
                    ldmatrix_x4(r,
                        sB + (wn * 64 + jj * 16 + bx_row_off) * 80 + s * 32 + bx_k_off);
                    bfrag[jj * 2][0]     = r[0]; bfrag[jj * 2][1]     = r[1];
                    bfrag[jj * 2 + 1][0] = r[2]; bfrag[jj * 2 + 1][1] = r[3];
                }
#pragma unroll
                for (int i = 0; i < 4; i++)
#pragma unroll
                    for (int j = 0; j < 8; j++)
                        mma16816(acc[i][j], afrag[i], bfrag[j]);
            }
            __syncthreads();
        }
    }
};

// ---------------------------------------------------------------------------
// merged projection kernel: blockIdx.z = 0:Q, 1:K, 2:V. cols = INNER always.
// z=0: rows=ROWS_Q, K=QD, scale=SCALE, normal hi/lo out.
// z=1: rows=ROWS_K, K=KD, normal hi/lo out.
// z=2: rows=ROWS_K, K=KD, per-head-transposed hi/lo out (vt[bh*64+c][m]).
// ---------------------------------------------------------------------------
__global__ void __launch_bounds__(128, 2)
gemm_proj(const __nv_bfloat16* __restrict__ xhi, const __nv_bfloat16* __restrict__ xlo,
          const __nv_bfloat16* __restrict__ khi, const __nv_bfloat16* __restrict__ klo,
          const __nv_bfloat16* __restrict__ vhi, const __nv_bfloat16* __restrict__ vlo,
          const __nv_bfloat16* __restrict__ wqhi, const __nv_bfloat16* __restrict__ wqlo,
          const __nv_bfloat16* __restrict__ wkhi, const __nv_bfloat16* __restrict__ wklo,
          const __nv_bfloat16* __restrict__ wvhi, const __nv_bfloat16* __restrict__ wvlo,
          __nv_bfloat16* __restrict__ qhi, __nv_bfloat16* __restrict__ qlo,
          __nv_bfloat16* __restrict__ kphi, __nv_bfloat16* __restrict__ kplo,
          __nv_bfloat16* __restrict__ vthi, __nv_bfloat16* __restrict__ vtlo)
{
    const int z = blockIdx.z;
    if (z > 0 && blockIdx.y >= ROWS_K / 128) return;

    const __nv_bfloat16 *Ahi, *Alo, *Bhi, *Blo;
    __nv_bfloat16 *Chi, *Clo;
    int K;
    float ascale = 1.0f;
    if (z == 0) {
        Ahi = xhi; Alo = xlo; Bhi = wqhi; Blo = wqlo;
        Chi = qhi; Clo = qlo; K = QD; ascale = SCALE;
    } else if (z == 1) {
        Ahi = khi; Alo = klo; Bhi = wkhi; Blo = wklo;
        Chi = kphi; Clo = kplo; K = KD;
    } else {
        Ahi = vhi; Alo = vlo; Bhi = wvhi; Blo = wvlo;
        Chi = vthi; Clo = vtlo; K = KD;
    }

    extern __shared__ char smem[];
    GemmCore core;
    core.init(smem_u32(smem), threadIdx.x);

    const int rbase = blockIdx.y * 128;
    const int cbase = blockIdx.x * 128;

    float acc[4][8][4];
#pragma unroll
    for (int i = 0; i < 4; i++)
#pragma unroll
        for (int j = 0; j < 8; j++)
#pragma unroll
            for (int e = 0; e < 4; e++) acc[i][j][e] = 0.0f;

    core.run<false>(acc, Ahi, Alo, Bhi, Blo, rbase, cbase, INNER, K);

    const int qrow = core.lane >> 2;
    const int qcol = (core.lane & 3) * 2;
    if (z < 2) {
#pragma unroll
        for (int i = 0; i < 4; i++) {
            const int row0 = rbase + core.wm * 64 + i * 16 + qrow;
#pragma unroll
            for (int j = 0; j < 8; j++) {
                const int col0 = cbase + core.wn * 64 + j * 8 + qcol;
                split_store2(Chi, Clo, (size_t)row0 * INNER + col0,
                             acc[i][j][0] * ascale, acc[i][j][1] * ascale);
                split_store2(Chi, Clo, (size_t)(row0 + 8) * INNER + col0,
                             acc[i][j][2] * ascale, acc[i][j][3] * ascale);
            }
        }
    } else {
#pragma unroll
        for (int i = 0; i < 4; i++) {
            const int row0 = rbase + core.wm * 64 + i * 16 + qrow;
#pragma unroll
            for (int j = 0; j < 8; j++) {
                const int col0 = cbase + core.wn * 64 + j * 8 + qcol;
#pragma unroll
                for (int rr = 0; rr < 2; rr++) {
                    const int r = row0 + rr * 8;
                    const int bb = r / M_SZ;
                    const int m  = r - bb * M_SZ;
#pragma unroll
                    for (int cc = 0; cc < 2; cc++) {
                        const int col = col0 + cc;
                        const int idx = (bb * HEADS + (col >> 6)) * CDIM + (col & 63);
                        const float v = acc[i][j][rr * 2 + cc];
                        __nv_bfloat16 h = __float2bfloat16(v);
                        Chi[(size_t)idx * M_SZ + m] = h;
                        Clo[(size_t)idx * M_SZ + m] =
                            __float2bfloat16(v - __bfloat162float(h));
                    }
                }
            }
        }
    }
}

// ---------------------------------------------------------------------------
// output projection: out = ao @ Wo^T + bo (cols=320, guard needed)
// ---------------------------------------------------------------------------
__global__ void __launch_bounds__(128, 2)
gemm_out(const __nv_bfloat16* __restrict__ Ahi, const __nv_bfloat16* __restrict__ Alo,
         const __nv_bfloat16* __restrict__ Bhi, const __nv_bfloat16* __restrict__ Blo,
         const float* __restrict__ bias, float* __restrict__ Cf)
{
    extern __shared__ char smem[];
    GemmCore core;
    core.init(smem_u32(smem), threadIdx.x);

    const int rbase = blockIdx.y * 128;
    const int cbase = blockIdx.x * 128;

    float acc[4][8][4];
#pragma unroll
    for (int i = 0; i < 4; i++)
#pragma unroll
        for (int j = 0; j < 8; j++)
#pragma unroll
            for (int e = 0; e < 4; e++) acc[i][j][e] = 0.0f;

    core.run<true>(acc, Ahi, Alo, Bhi, Blo, rbase, cbase, QD, INNER);

    const int qrow = core.lane >> 2;
    const int qcol = (core.lane & 3) * 2;
#pragma unroll
    for (int i = 0; i < 4; i++) {
        const int row0 = rbase + core.wm * 64 + i * 16 + qrow;
#pragma unroll
        for (int j = 0; j < 8; j++) {
            const int col0 = cbase + core.wn * 64 + j * 8 + qcol;
            if (col0 >= QD) continue;
            const float b0 = bias[col0], b1 = bias[col0 + 1];
            *(float2*)(Cf + (size_t)row0 * QD + col0) =
                make_float2(acc[i][j][0] + b0, acc[i][j][1] + b1);
            *(float2*)(Cf + (size_t)(row0 + 8) * QD + col0) =
                make_float2(acc[i][j][2] + b0, acc[i][j][3] + b1);
        }
    }
}

// ---------------------------------------------------------------------------
// Fused attention (unchanged from R6, validated): per (b,h,ntile=128):
// S = QK^T, mask + box bias, softmax, P SMEM-resident, O = P*Vt.
// ---------------------------------------------------------------------------
#define AT_QBUF  16384
#define AT_KBASE 32768
#define AT_KBUF  10240
#define AT_BOX   53248
#define AT_RED   94208
#define AT_P     32768
#define AT_PBUF  22528
#define AT_VBUF  11264
#define AT_SMEM  96576

__global__ void __launch_bounds__(128, 2)
attn_fused(const __nv_bfloat16* __restrict__ qhi, const __nv_bfloat16* __restrict__ qlo,
           const __nv_bfloat16* __restrict__ khi, const __nv_bfloat16* __restrict__ klo,
           const __nv_bfloat16* __restrict__ vthi, const __nv_bfloat16* __restrict__ vtlo,
           const int* __restrict__ mask, const float* __restrict__ box,
           __nv_bfloat16* __restrict__ aohi, __nv_bfloat16* __restrict__ aolo)
{
    extern __shared__ char smem[];
    const uint32_t sbase = smem_u32(smem);
    const int tid  = threadIdx.x;
    const int wid  = tid >> 5;
    const int lane = tid & 31;
    const int wr   = wid >> 1;
    const int wc   = wid & 1;
    const int bh   = blockIdx.y;
    const int b    = bh >> 3, h = bh & 7;
    const int nbase = blockIdx.x * 128;

    int* smask = (int*)(smem + AT_RED + 2048);
    if (tid < M_SZ) smask[tid] = mask[b * M_SZ + tid];

    const __nv_bfloat16* qsrc[2] = {qhi, qlo};
#pragma unroll
    for (int u = 0; u < 16; u++) {
        const int task = u * 128 + tid;
        const int buf  = task >> 10;
        const int rem  = task & 1023;
        const int row  = rem >> 3, ch = rem & 7;
        cp_async16(sbase + buf * AT_QBUF + SWZ(row * 128 + ch * 16),
                   qsrc[buf] + (size_t)(b * N_SZ + nbase + row) * INNER + h * CDIM + ch * 8, 16);
    }
    const __nv_bfloat16* ksrc[2] = {khi, klo};
#pragma unroll
    for (int u = 0; u < 10; u++) {
        const int task = u * 128 + tid;
        const int buf  = task >= 640;
        const int rem  = task - buf * 640;
        const int row  = rem >> 3, ch = rem & 7;
        cp_async16(sbase + AT_KBASE + buf * AT_KBUF + SWZ(row * 128 + ch * 16),
                   ksrc[buf] + (size_t)(b * M_SZ + row) * INNER + h * CDIM + ch * 8, 16);
    }
#pragma unroll
    for (int u = 0; u < 20; u++) {
        const int task = u * 128 + tid;
        const int row  = task / 20, ch = task - row * 20;
        cp_async16(sbase + AT_BOX + row * 320 + ch * 16,
                   box + (size_t)(b * N_SZ + nbase + row) * M_SZ + ch * 4, 16);
    }
    cp_commit();
    cp_wait<0>();
    __syncthreads();

    const int g  = lane >> 3;
    const int r8 = lane & 7;
    const int a_row_off = (g & 1) * 8 + r8;
    const int a_k_off   = (g >> 1) * 16;

    float acc[4][5][4];
#pragma unroll
    for (int i = 0; i < 4; i++)
#pragma unroll
        for (int j = 0; j < 5; j++)
#pragma unroll
            for (int e = 0; e < 4; e++) acc[i][j][e] = 0.0f;

#pragma unroll
    for (int p = 0; p < 3; p++) {
        const uint32_t qb = sbase + ((p == 2) ? AT_QBUF : 0);
        const uint32_t kb = sbase + AT_KBASE + ((p == 1) ? AT_KBUF : 0);
#pragma unroll
        for (int ks = 0; ks < 4; ks++) {
            uint32_t af[4][4], bf[5][2];
#pragma unroll
            for (int i = 0; i < 4; i++)
                ldmatrix_x4(af[i], qb + SWZ((wr * 64 + i * 16 + a_row_off) * 128
                                            + ks * 32 + a_k_off));
#pragma unroll
            for (int j = 0; j < 5; j++)
                ldmatrix_x2(bf[j], kb + SWZ((wc * 40 + j * 8 + r8) * 128
                                            + ks * 32 + (g & 1) * 16));
#pragma unroll
            for (int i = 0; i < 4; i++)
#pragma unroll
                for (int j = 0; j < 5; j++)
                    mma16816(acc[i][j], af[i], bf[j]);
        }
    }
    __syncthreads();

    const __nv_bfloat16* vsrc[2] = {vthi, vtlo};
#pragma unroll
    for (int u = 0; u < 10; u++) {
        const int task = u * 128 + tid;
        const int buf  = task >= 640;
        const int rem  = task - buf * 640;
        const int row  = rem / 10, ch = rem - row * 10;
        cp_async16(sbase + buf * AT_VBUF + row * 176 + ch * 16,
                   vsrc[buf] + ((size_t)bh * CDIM + row) * M_SZ + ch * 8, 16);
    }
    cp_commit();

    const float* boxS = (const float*)(smem + AT_BOX);
    const int qrow = lane >> 2;
    const int qcol = (lane & 3) * 2;
#pragma unroll
    for (int i = 0; i < 4; i++)
#pragma unroll
        for (int j = 0; j < 5; j++)
#pragma unroll
            for (int e = 0; e < 4; e++) {
                const int r = wr * 64 + i * 16 + qrow + (e >> 1) * 8;
                const int c = wc * 40 + j * 8 + qcol + (e & 1);
                acc[i][j][e] = smask[c]
                    ? acc[i][j][e] + LAMDA1 * boxS[r * 80 + c] : BIGNEG;
            }

    float* rmax = (float*)(smem + AT_RED);
    float* rsum = rmax + 256;
    float rm[4][2];
#pragma unroll
    for (int i = 0; i < 4; i++)
#pragma unroll
        for (int hf = 0; hf < 2; hf++) {
            float m = BIGNEG;
#pragma unroll
            for (int j = 0; j < 5; j++)
                m = fmaxf(m, fmaxf(acc[i][j][hf * 2], acc[i][j][hf * 2 + 1]));
            m = fmaxf(m, __shfl_xor_sync(0xffffffffu, m, 1));
            m = fmaxf(m, __shfl_xor_sync(0xffffffffu, m, 2));
            rm[i][hf] = m;
        }
    if ((lane & 3) == 0)
#pragma unroll
        for (int i = 0; i < 4; i++)
#pragma unroll
            for (int hf = 0; hf < 2; hf++)
                rmax[wc * 128 + wr * 64 + i * 16 + qrow + hf * 8] = rm[i][hf];
    __syncthreads();

    float rs[4][2];
#pragma unroll
    for (int i = 0; i < 4; i++)
#pragma unroll
        for (int hf = 0; hf < 2; hf++) {
            const int r = wr * 64 + i * 16 + qrow + hf * 8;
            const float m = fmaxf(rmax[r], rmax[128 + r]);
            float s = 0.0f;
#pragma unroll
            for (int j = 0; j < 5; j++) {
                acc[i][j][hf * 2]     = __expf(acc[i][j][hf * 2]     - m);
                acc[i][j][hf * 2 + 1] = __expf(acc[i][j][hf * 2 + 1] - m);
                s += acc[i][j][hf * 2] + acc[i][j][hf * 2 + 1];
            }
            s += __shfl_xor_sync(0xffffffffu, s, 1);
            s += __shfl_xor_sync(0xffffffffu, s, 2);
            rs[i][hf] = s;
        }
    if ((lane & 3) == 0)
#pragma unroll
        for (int i = 0; i < 4; i++)
#pragma unroll
            for (int hf = 0; hf < 2; hf++)
                rsum[wc * 128 + wr * 64 + i * 16 + qrow + hf * 8] = rs[i][hf];
    __syncthreads();

#pragma unroll
    for (int i = 0; i < 4; i++)
#pragma unroll
        for (int hf = 0; hf < 2; hf++) {
            const int r = wr * 64 + i * 16 + qrow + hf * 8;
            const float inv = 1.0f / (rsum[r] + rsum[128 + r]);
#pragma unroll
            for (int j = 0; j < 5; j++) {
                const int c0 = wc * 40 + j * 8 + qcol;
                const float p0 = acc[i][j][hf * 2] * inv;
                const float p1 = acc[i][j][hf * 2 + 1] * inv;
                __nv_bfloat16 h0 = __float2bfloat16(p0);
                __nv_bfloat16 h1 = __float2bfloat16(p1);
                *(__nv_bfloat162*)(smem + AT_P + r * 176 + c0 * 2) =
                    __halves2bfloat162(h0, h1);
                *(__nv_bfloat162*)(smem + AT_P + AT_PBUF + r * 176 + c0 * 2) =
                    __halves2bfloat162(
                        __float2bfloat16(p0 - __bfloat162float(h0)),
                        __float2bfloat16(p1 - __bfloat162float(h1)));
            }
        }
    cp_wait<0>();
    __syncthreads();

    float acc2[4][4][4];
#pragma unroll
    for (int i = 0; i < 4; i++)
#pragma unroll
        for (int j = 0; j < 4; j++)
#pragma unroll
            for (int e = 0; e < 4; e++) acc2[i][j][e] = 0.0f;

#pragma unroll
    for (int p = 0; p < 3; p++) {
        const uint32_t pb = sbase + AT_P + ((p == 2) ? AT_PBUF : 0);
        const uint32_t vb = sbase + ((p == 1) ? AT_VBUF : 0);
#pragma unroll
        for (int ks = 0; ks < 5; ks++) {
            uint32_t af[4][4], bf[4][2];
#pragma unroll
            for (int i = 0; i < 4; i++)
                ldmatrix_x4(af[i], pb + (wr * 64 + i * 16 + a_row_off) * 176
                                      + ks * 32 + a_k_off);
#pragma unroll
            for (int j = 0; j < 4; j++)
                ldmatrix_x2(bf[j], vb + (wc * 32 + j * 8 + r8) * 176
                                      + ks * 32 + (g & 1) * 16);
#pragma unroll
            for (int i = 0; i < 4; i++)
#pragma unroll
                for (int j = 0; j < 4; j++)
                    mma16816(acc2[i][j], af[i], bf[j]);
        }
    }

#pragma unroll
    for (int i = 0; i < 4; i++) {
        const int n0 = nbase + wr * 64 + i * 16 + qrow;
#pragma unroll
        for (int j = 0; j < 4; j++) {
            const int c0 = wc * 32 + j * 8 + qcol;
            const size_t i0 = (size_t)(b * N_SZ + n0) * INNER + h * CDIM + c0;
            split_store2(aohi, aolo, i0,                     acc2[i][j][0], acc2[i][j][1]);
            split_store2(aohi, aolo, i0 + (size_t)8 * INNER, acc2[i][j][2], acc2[i][j][3]);
        }
    }
}

// ---------------------------------------------------------------------------
// Launch (4 kernels total)
// ---------------------------------------------------------------------------
extern "C" void kernel_launch(void* const* d_in, const int* in_sizes, int n_in,
                              void* d_out, int out_size)
{
    const float* x    = (const float*)d_in[0];
    const float* key  = (const float*)d_in[1];
    const float* val  = (const float*)d_in[2];
    const int*   mask = (const int*)d_in[3];
    const float* box  = (const float*)d_in[4];
    // d_in[5] road map: softmax-invariant, unused
    const float* Wq   = (const float*)d_in[6];
    const float* Wk   = (const float*)d_in[7];
    const float* Wv   = (const float*)d_in[8];
    const float* Wo   = (const float*)d_in[9];
    const float* bo   = (const float*)d_in[10];
    float*       out  = (float*)d_out;

    __nv_bfloat16 *xhi, *xlo, *khi, *klo, *vhi, *vlo;
    __nv_bfloat16 *wqhi, *wqlo, *wkhi, *wklo, *wvhi, *wvlo, *wohi, *wolo;
    __nv_bfloat16 *qhi, *qlo, *kphi, *kplo, *vthi, *vtlo, *aohi, *aolo;
    cudaGetSymbolAddress((void**)&xhi, g_xhi);   cudaGetSymbolAddress((void**)&xlo, g_xlo);
    cudaGetSymbolAddress((void**)&khi, g_khi);   cudaGetSymbolAddress((void**)&klo, g_klo);
    cudaGetSymbolAddress((void**)&vhi, g_vhi);   cudaGetSymbolAddress((void**)&vlo, g_vlo);
    cudaGetSymbolAddress((void**)&wqhi, g_wqhi); cudaGetSymbolAddress((void**)&wqlo, g_wqlo);
    cudaGetSymbolAddress((void**)&wkhi, g_wkhi); cudaGetSymbolAddress((void**)&wklo, g_wklo);
    cudaGetSymbolAddress((void**)&wvhi, g_wvhi); cudaGetSymbolAddress((void**)&wvlo, g_wvlo);
    cudaGetSymbolAddress((void**)&wohi, g_wohi); cudaGetSymbolAddress((void**)&wolo, g_wolo);
    cudaGetSymbolAddress((void**)&qhi, g_qhi);   cudaGetSymbolAddress((void**)&qlo, g_qlo);
    cudaGetSymbolAddress((void**)&kphi, g_kphi); cudaGetSymbolAddress((void**)&kplo, g_kplo);
    cudaGetSymbolAddress((void**)&vthi, g_vthi); cudaGetSymbolAddress((void**)&vtlo, g_vtlo);
    cudaGetSymbolAddress((void**)&aohi, g_aohi); cudaGetSymbolAddress((void**)&aolo, g_aolo);

    constexpr int SMEM_G = 3 * 2 * STAGE_B;     // 61440
    cudaFuncSetAttribute(gemm_proj, cudaFuncAttributeMaxDynamicSharedMemorySize, SMEM_G);
    cudaFuncSetAttribute(gemm_out,  cudaFuncAttributeMaxDynamicSharedMemorySize, SMEM_G);
    cudaFuncSetAttribute(attn_fused, cudaFuncAttributeMaxDynamicSharedMemorySize, AT_SMEM);

    // 1) all splits in one launch
    split_all<<<(S7 + 255) / 256, 256>>>(
        x, key, val, Wq, Wk, Wv, Wo,
        xhi, xlo, khi, klo, vhi, vlo,
        wqhi, wqlo, wkhi, wklo, wvhi, wvlo, wohi, wolo);

    // 2) all three projections in one launch (z: 0=Q, 1=K, 2=V)
    gemm_proj<<<dim3(INNER / 128, ROWS_Q / 128, 3), 128, SMEM_G>>>(
        xhi, xlo, khi, klo, vhi, vlo,
        wqhi, wqlo, wkhi, wklo, wvhi, wvlo,
        qhi, qlo, kphi, kplo, vthi, vtlo);

    // 3) fused attention
    attn_fused<<<dim3(N_SZ / 128, B_SZ * HEADS), 128, AT_SMEM>>>(
        qhi, qlo, kphi, kplo, vthi, vtlo, mask, box, aohi, aolo);

    // 4) output projection + bias
    gemm_out<<<dim3((QD + 127) / 128, ROWS_Q / 128), 128, SMEM_G>>>(
        aohi, aolo, wohi, wolo, bo, out);
}